// round 1
// baseline (speedup 1.0000x reference)
#include <cuda_runtime.h>
#include <math.h>

#define T_   8192
#define H_   2048
#define NH_  16
#define NKV_ 4
#define D_   128
#define CH   64
#define NC   128          // T_/CH
#define QKVW 3072         // (NH + 2*NKV)*D

// ---------------- scratch (static device memory; no allocs allowed) ----------
__device__ float g_qkv[(size_t)T_ * QKVW];        // qkv projection, then q~ / k~ / v in place
__device__ float g_tmp16[(size_t)T_ * 16];        // hidden @ gk_w0
__device__ float g_g[(size_t)T_ * 512];           // log-gates g = logsigmoid(gk)/16
__device__ float g_B[(size_t)T_ * 512];           // in-chunk cumsum of g
__device__ float g_P[(size_t)NC * NKV_ * D_ * D_];// per-chunk state increment
__device__ float g_S[(size_t)NC * NKV_ * D_ * D_];// state at chunk start
__device__ float g_o[(size_t)T_ * 2048];          // attention output pre-o_proj

// ---------------- generic fp32 SGEMM: C = A[MxK] @ B[KxN] (+bias) ------------
// BM=BN=128, BK=8, TM=TN=8, 256 threads. All dims multiples of 128/8.
__global__ void __launch_bounds__(256) sgemm128(const float* __restrict__ A,
                                                const float* __restrict__ B,
                                                const float* __restrict__ bias,
                                                float* __restrict__ C,
                                                int M, int N, int K) {
    __shared__ float As[8][128];
    __shared__ float Bs[8][128];
    int tid = threadIdx.x;
    int brow = blockIdx.y, bcol = blockIdx.x;
    const float* Ab = A + (size_t)brow * 128 * K;
    const float* Bb = B + (size_t)bcol * 128;

    int arow = tid >> 1, acol = (tid & 1) << 2;          // A: 128 rows x 8 k
    int brl  = tid >> 5, bcl  = (tid & 31) << 2;         // B: 8 rows x 128 cols

    float acc[8][8];
#pragma unroll
    for (int i = 0; i < 8; i++)
#pragma unroll
        for (int j = 0; j < 8; j++) acc[i][j] = 0.f;

    int tr = (tid >> 4) << 3;
    int tc = (tid & 15) << 3;

    for (int k0 = 0; k0 < K; k0 += 8) {
        float4 a4 = *(const float4*)(Ab + (size_t)arow * K + k0 + acol);
        As[acol + 0][arow] = a4.x;
        As[acol + 1][arow] = a4.y;
        As[acol + 2][arow] = a4.z;
        As[acol + 3][arow] = a4.w;
        *(float4*)&Bs[brl][bcl] = *(const float4*)(Bb + (size_t)(k0 + brl) * N + bcl);
        __syncthreads();
#pragma unroll
        for (int k = 0; k < 8; k++) {
            float am[8], bn[8];
#pragma unroll
            for (int i = 0; i < 8; i++) am[i] = As[k][tr + i];
#pragma unroll
            for (int j = 0; j < 8; j++) bn[j] = Bs[k][tc + j];
#pragma unroll
            for (int i = 0; i < 8; i++)
#pragma unroll
                for (int j = 0; j < 8; j++) acc[i][j] += am[i] * bn[j];
        }
        __syncthreads();
    }

#pragma unroll
    for (int i = 0; i < 8; i++) {
        float* Crow = C + (size_t)(brow * 128 + tr + i) * N + bcol * 128 + tc;
        if (bias) {
            const float* bp = bias + bcol * 128 + tc;
#pragma unroll
            for (int j = 0; j < 8; j++) Crow[j] = acc[i][j] + bp[j];
        } else {
#pragma unroll
            for (int j = 0; j < 8; j++) Crow[j] = acc[i][j];
        }
    }
}

// ---------------- gate low-rank projections -----------------------------------
// tmp[t][r] = sum_h hidden[t][h] * w0[h][r]    (R=16)
__global__ void __launch_bounds__(256) gk1_kernel(const float* __restrict__ hidden,
                                                  const float* __restrict__ w0) {
    int t = blockIdx.x, tid = threadIdx.x;
    float acc[16];
#pragma unroll
    for (int r = 0; r < 16; r++) acc[r] = 0.f;
    const float* hrow = hidden + (size_t)t * H_;
    for (int h = tid; h < H_; h += 256) {
        float x = hrow[h];
        const float4* w = (const float4*)(w0 + (size_t)h * 16);
#pragma unroll
        for (int q = 0; q < 4; q++) {
            float4 w4 = w[q];
            acc[q * 4 + 0] += x * w4.x;
            acc[q * 4 + 1] += x * w4.y;
            acc[q * 4 + 2] += x * w4.z;
            acc[q * 4 + 3] += x * w4.w;
        }
    }
    __shared__ float sred[256][16];
#pragma unroll
    for (int r = 0; r < 16; r++) sred[tid][r] = acc[r];
    __syncthreads();
    if (tid < 16) {
        float s = 0.f;
        for (int i = 0; i < 256; i++) s += sred[i][tid];
        g_tmp16[(size_t)t * 16 + tid] = s;
    }
}

// g[t][n] = logsigmoid( tmp[t] @ w1[:,n] + b1[n] ) / 16
__global__ void __launch_bounds__(256) gk2_kernel(const float* __restrict__ w1,
                                                  const float* __restrict__ b1) {
    int idx = blockIdx.x * 256 + threadIdx.x;      // T_*512 threads
    int t = idx >> 9, n = idx & 511;
    const float* tp = g_tmp16 + (size_t)t * 16;
    float x = b1[n];
#pragma unroll
    for (int r = 0; r < 16; r++) x += tp[r] * w1[r * 512 + n];
    float ls = (x >= 0.f) ? (-log1pf(expf(-x))) : (x - log1pf(expf(x)));
    g_g[(size_t)t * 512 + n] = ls * (1.f / 16.f);
}

// ---------------- relu(q)*scale, relu(k) in place ------------------------------
__global__ void __launch_bounds__(256) prep_kernel() {
    int idx = blockIdx.x * 256 + threadIdx.x;      // T_*2560 threads
    int t = idx / 2560, c = idx % 2560;
    size_t a = (size_t)t * QKVW + c;
    float v = g_qkv[a];
    v = fmaxf(v, 0.f);
    if (c < 2048) v *= 0.08838834764831843f;       // D^-0.5
    g_qkv[a] = v;
}

// ---------------- per-chunk cumsum + pre-scale q~ / k~ in place ----------------
// grid (NC, NKV), 128 threads (one per d)
__global__ void __launch_bounds__(128) chunkB_kernel() {
    int c = blockIdx.x, kv = blockIdx.y, d = threadIdx.x;
    float cum = 0.f;
    for (int t = 0; t < CH; t++) {
        size_t tg = (size_t)c * CH + t;
        size_t gi = tg * 512 + kv * 128 + d;
        cum += g_g[gi];
        g_B[gi] = cum;
        float eB = expf(cum), eBn = expf(-cum);
        size_t rb = tg * QKVW;
        g_qkv[rb + 2048 + kv * 128 + d] *= eBn;            // k~ = relu(k)*exp(-B)
#pragma unroll
        for (int r = 0; r < 4; r++)
            g_qkv[rb + (kv * 4 + r) * 128 + d] *= eB;      // q~ = q*scale*exp(B)
    }
}

// ---------------- per-chunk increment P = exp(Btot) ⊙ (K~^T V) ----------------
// grid (NC, NKV), 256 threads: thread owns (dk, half of dv)
__global__ void __launch_bounds__(256) chunkP_kernel() {
    __shared__ float sv[CH * 128];
    int c = blockIdx.x, kv = blockIdx.y, tid = threadIdx.x;
    for (int i = tid; i < CH * 32; i += 256) {
        int r = i >> 5, c4 = i & 31;
        ((float4*)sv)[i] = *(const float4*)(g_qkv + ((size_t)(c * CH + r)) * QKVW +
                                            2560 + kv * 128 + c4 * 4);
    }
    __syncthreads();
    int dk = tid >> 1, half = (tid & 1) * 64;
    float acc[64];
#pragma unroll
    for (int j = 0; j < 64; j++) acc[j] = 0.f;
    for (int t = 0; t < CH; t++) {
        float kk = g_qkv[((size_t)(c * CH + t)) * QKVW + 2048 + kv * 128 + dk];
        const float* vr = sv + t * 128 + half;
#pragma unroll
        for (int j = 0; j < 64; j++) acc[j] += kk * vr[j];
    }
    float eb = expf(g_B[((size_t)(c * CH + CH - 1)) * 512 + kv * 128 + dk]);
    float* pp = g_P + (((size_t)(c * 4 + kv)) * 128 + dk) * 128 + half;
#pragma unroll
    for (int j = 0; j < 64; j++) pp[j] = acc[j] * eb;
}

// ---------------- sequential inter-chunk combine -------------------------------
// 16 blocks: (kv, 32-col slice). S slice lives in registers.
__global__ void __launch_bounds__(256) combine_kernel() {
    int kv = blockIdx.x >> 2, slice = blockIdx.x & 3;
    int tid = threadIdx.x;
    int dvl = tid & 31, dkg = tid >> 5;
    float S[16];
#pragma unroll
    for (int i = 0; i < 16; i++) S[i] = 0.f;
    for (int c = 0; c < NC; c++) {
        size_t base = ((size_t)(c * 4 + kv)) * 128 * 128;
        const float* Bt = g_B + ((size_t)(c * CH + CH - 1)) * 512 + kv * 128;
#pragma unroll
        for (int i = 0; i < 16; i++) {
            int dk = dkg * 16 + i;
            size_t idx = base + (size_t)dk * 128 + slice * 32 + dvl;
            g_S[idx] = S[i];
            float eb = expf(Bt[dk]);
            S[i] = eb * S[i] + g_P[idx];
        }
    }
}

// ---------------- intra-chunk output: o = Q~ S_c + mask(Q~ K~^T) V, + RMSNorm --
// grid (NC, NH), 256 threads. Static smem = 48KB exactly.
__global__ void __launch_bounds__(256) out_kernel(const float* __restrict__ gnw) {
    __shared__ float sK[CH * 128];
    __shared__ float sA[CH * CH];
    int c = blockIdx.x, h = blockIdx.y, kv = h >> 2;
    int tid = threadIdx.x;
    const float* qb = g_qkv + (size_t)c * CH * QKVW + h * 128;
    const float* kb = g_qkv + (size_t)c * CH * QKVW + 2048 + kv * 128;
    const float* vb = g_qkv + (size_t)c * CH * QKVW + 2560 + kv * 128;

    for (int i = tid; i < CH * 32; i += 256) {
        int r = i >> 5, c4 = i & 31;
        ((float4*)sK)[i] = *(const float4*)(kb + (size_t)r * QKVW + c4 * 4);
    }
    __syncthreads();

    // phase 1: A[t][s] = q~[t] . k~[s], causal mask
    {
        int t = tid >> 2, sq = (tid & 3) << 4;
        float a[16];
#pragma unroll
        for (int j = 0; j < 16; j++) a[j] = 0.f;
        const float* qr = qb + (size_t)t * QKVW;
        for (int dk = 0; dk < 128; dk++) {
            float qv = __ldg(qr + dk);
#pragma unroll
            for (int j = 0; j < 16; j++) a[j] += qv * sK[(sq + j) * 128 + dk];
        }
#pragma unroll
        for (int j = 0; j < 16; j++)
            sA[t * CH + sq + j] = (sq + j <= t) ? a[j] : 0.f;
    }
    __syncthreads();

    // phase 2: o[t][dv]
    const float* Sb = g_S + ((size_t)(c * 4 + kv)) * 128 * 128;
    int t = tid >> 2, dq = (tid & 3) << 5;
    float acc[32];
#pragma unroll
    for (int j = 0; j < 32; j++) acc[j] = 0.f;
    const float* qr = qb + (size_t)t * QKVW;
    for (int dk = 0; dk < 128; dk++) {
        float qv = __ldg(qr + dk);
        const float4* s4 = (const float4*)(Sb + (size_t)dk * 128 + dq);
#pragma unroll
        for (int j4 = 0; j4 < 8; j4++) {
            float4 s = __ldg(s4 + j4);
            acc[j4 * 4 + 0] += qv * s.x;
            acc[j4 * 4 + 1] += qv * s.y;
            acc[j4 * 4 + 2] += qv * s.z;
            acc[j4 * 4 + 3] += qv * s.w;
        }
    }
    for (int s = 0; s < CH; s++) {
        float a = sA[t * CH + s];
        const float4* v4 = (const float4*)(vb + (size_t)s * QKVW + dq);
#pragma unroll
        for (int j4 = 0; j4 < 8; j4++) {
            float4 v = __ldg(v4 + j4);
            acc[j4 * 4 + 0] += a * v.x;
            acc[j4 * 4 + 1] += a * v.y;
            acc[j4 * 4 + 2] += a * v.z;
            acc[j4 * 4 + 3] += a * v.w;
        }
    }
    // fused RMSNorm over head_dim (4 lanes per row)
    float ss = 0.f;
#pragma unroll
    for (int j = 0; j < 32; j++) ss += acc[j] * acc[j];
    ss += __shfl_xor_sync(0xffffffffu, ss, 1);
    ss += __shfl_xor_sync(0xffffffffu, ss, 2);
    float rn = rsqrtf(ss * (1.f / 128.f) + 1e-6f);
    size_t tg = (size_t)c * CH + t;
    float* orow = g_o + tg * 2048 + h * 128 + dq;
#pragma unroll
    for (int j = 0; j < 32; j++) orow[j] = acc[j] * rn * __ldg(gnw + dq + j);
}

// ---------------- launch -------------------------------------------------------
extern "C" void kernel_launch(void* const* d_in, const int* in_sizes, int n_in,
                              void* d_out, int out_size) {
    const float* hidden = (const float*)d_in[0];
    const float* Wqkv   = (const float*)d_in[1];
    const float* bqkv   = (const float*)d_in[2];
    const float* gk_w0  = (const float*)d_in[3];
    const float* gk_w1  = (const float*)d_in[4];
    const float* gk_b1  = (const float*)d_in[5];
    const float* gnormw = (const float*)d_in[6];
    const float* Wo     = (const float*)d_in[7];
    float* out = (float*)d_out;

    float *p_qkv, *p_o;
    cudaGetSymbolAddress((void**)&p_qkv, g_qkv);
    cudaGetSymbolAddress((void**)&p_o, g_o);

    // 1) qkv = hidden @ Wqkv + bqkv
    sgemm128<<<dim3(QKVW / 128, T_ / 128), 256>>>(hidden, Wqkv, bqkv, p_qkv,
                                                  T_, QKVW, H_);
    // 2) gate projections
    gk1_kernel<<<T_, 256>>>(hidden, gk_w0);
    gk2_kernel<<<(T_ * 512) / 256, 256>>>(gk_w1, gk_b1);
    // 3) relu/scale q,k
    prep_kernel<<<(T_ * 2560) / 256, 256>>>();
    // 4) chunk cumsum + prescale
    chunkB_kernel<<<dim3(NC, NKV_), 128>>>();
    // 5) chunk increments
    chunkP_kernel<<<dim3(NC, NKV_), 256>>>();
    // 6) sequential combine across chunks
    combine_kernel<<<16, 256>>>();
    // 7) intra-chunk outputs + RMSNorm
    out_kernel<<<dim3(NC, NH_), 256>>>(gnormw);
    // 8) out = o @ Wo
    sgemm128<<<dim3(H_ / 128, T_ / 128), 256>>>(p_o, Wo, nullptr, out,
                                                T_, H_, H_);
}

// round 3
// speedup vs baseline: 1.5746x; 1.5746x over previous
#include <cuda_runtime.h>
#include <cuda_bf16.h>
#include <cstdint>
#include <math.h>

#define T_   8192
#define H_   2048
#define NH_  16
#define NKV_ 4
#define D_   128
#define CH   64
#define NC   128          // T_/CH
#define QKVW 3072         // (NH + 2*NKV)*D
#define GK   2048         // true K of both big GEMMs
#define NKC  192          // K_ext/32 = 3*2048/32

// ---------------- scratch (static device memory; no allocs allowed) ----------
__device__ __align__(256) float g_qkv[(size_t)T_ * QKVW];
__device__ __align__(256) float g_tmp16[(size_t)T_ * 16];
__device__ __align__(256) float g_g[(size_t)T_ * 512];
__device__ __align__(256) float g_B[(size_t)T_ * 512];
__device__ __align__(256) float g_P[(size_t)NC * NKV_ * D_ * D_];
__device__ __align__(256) float g_S[(size_t)NC * NKV_ * D_ * D_];
__device__ __align__(256) float g_o[(size_t)T_ * 2048];
// bf16 hi/lo planes for tensor-core GEMMs
__device__ __align__(256) __nv_bfloat16 g_hAhi[(size_t)T_ * H_];
__device__ __align__(256) __nv_bfloat16 g_hAlo[(size_t)T_ * H_];
__device__ __align__(256) __nv_bfloat16 g_Wqhi[(size_t)QKVW * GK];   // [N,K]
__device__ __align__(256) __nv_bfloat16 g_Wqlo[(size_t)QKVW * GK];
__device__ __align__(256) __nv_bfloat16 g_Wohi[(size_t)H_ * GK];     // [N,K]
__device__ __align__(256) __nv_bfloat16 g_Wolo[(size_t)H_ * GK];
__device__ __align__(256) __nv_bfloat16 g_oAhi[(size_t)T_ * H_];
__device__ __align__(256) __nv_bfloat16 g_oAlo[(size_t)T_ * H_];

// ======================= small PTX helpers ====================================
__device__ __forceinline__ uint32_t smem_u32(const void* p) {
    uint32_t a;
    asm("{ .reg .u64 t; cvta.to.shared.u64 t, %1; cvt.u32.u64 %0, t; }" : "=r"(a) : "l"(p));
    return a;
}
__device__ __forceinline__ void cpa16(uint32_t dst, const void* src) {
    asm volatile("cp.async.cg.shared.global [%0], [%1], 16;" :: "r"(dst), "l"(src));
}
__device__ __forceinline__ void ldsm4(uint32_t* r, uint32_t addr) {
    asm volatile("ldmatrix.sync.aligned.m8n8.x4.shared.b16 {%0,%1,%2,%3}, [%4];"
                 : "=r"(r[0]), "=r"(r[1]), "=r"(r[2]), "=r"(r[3]) : "r"(addr));
}
__device__ __forceinline__ void mma16816(float* d, const uint32_t* a,
                                         uint32_t b0, uint32_t b1) {
    asm volatile("mma.sync.aligned.m16n8k16.row.col.f32.bf16.bf16.f32 "
                 "{%0,%1,%2,%3}, {%4,%5,%6,%7}, {%8,%9}, {%0,%1,%2,%3};"
                 : "+f"(d[0]), "+f"(d[1]), "+f"(d[2]), "+f"(d[3])
                 : "r"(a[0]), "r"(a[1]), "r"(a[2]), "r"(a[3]), "r"(b0), "r"(b1));
}

// ======================= fp32 -> bf16 hi/lo split =============================
__global__ void __launch_bounds__(256) split_kernel(const float* __restrict__ src,
                                                    __nv_bfloat16* __restrict__ hi,
                                                    __nv_bfloat16* __restrict__ lo) {
    size_t i = (size_t)blockIdx.x * 256 + threadIdx.x;
    float x = src[i];
    __nv_bfloat16 h = __float2bfloat16_rn(x);
    hi[i] = h;
    lo[i] = __float2bfloat16_rn(x - __bfloat162float(h));
}

// W [K=2048, N] row-major  ->  hi/lo [N, K=2048] bf16
__global__ void __launch_bounds__(256) wsplit_kernel(const float* __restrict__ W,
                                                     __nv_bfloat16* __restrict__ hi,
                                                     __nv_bfloat16* __restrict__ lo, int N) {
    __shared__ float t[32][33];
    int bx = blockIdx.x, by = blockIdx.y;
    int lx = threadIdx.x & 31, ly = threadIdx.x >> 5;
    for (int r = ly; r < 32; r += 8)
        t[r][lx] = W[(size_t)(by * 32 + r) * N + bx * 32 + lx];
    __syncthreads();
    for (int r = ly; r < 32; r += 8) {
        float x = t[lx][r];
        __nv_bfloat16 h = __float2bfloat16_rn(x);
        size_t idx = (size_t)(bx * 32 + r) * GK + by * 32 + lx;
        hi[idx] = h;
        lo[idx] = __float2bfloat16_rn(x - __bfloat162float(h));
    }
}

// ======================= HMMA GEMM (mma.sync, family-portable) =================
// C[M,N] = Ahi@Bhi^T + Ahi@Blo^T + Alo@Bhi^T  via K_ext = 3*2048.
// CTA tile 128x128, 8 warps (warp tile 64x32), K-chunk 32, 4-stage cp.async.
// smem rows padded to 80B (20r mod 32 distinct -> conflict-free ldmatrix).
#define ROWB   80
#define TILEB  (128 * ROWB)      // 10240 per operand
#define STAGEB (2 * TILEB)       // 20480
#define GSMEM  (4 * STAGEB)      // 81920

__global__ void __launch_bounds__(256) gemm_mma(
    const __nv_bfloat16* __restrict__ Ahi, const __nv_bfloat16* __restrict__ Alo,
    const __nv_bfloat16* __restrict__ Bhi, const __nv_bfloat16* __restrict__ Blo,
    const float* __restrict__ bias, float* __restrict__ C, int N, int mode) {
    extern __shared__ char smraw[];
    uint32_t sbase = smem_u32(smraw);
    int tid = threadIdx.x, wid = tid >> 5, lane = tid & 31;
    int tm = blockIdx.y * 128, tn = blockIdx.x * 128;
    int wm = wid & 1, wn = wid >> 1;

    float acc[4][4][4];
#pragma unroll
    for (int i = 0; i < 4; i++)
#pragma unroll
        for (int j = 0; j < 4; j++)
#pragma unroll
            for (int r = 0; r < 4; r++) acc[i][j][r] = 0.f;

    // ---- async loader: one 32-wide K chunk of A(128 rows) + B(128 rows) ----
    auto issue_load = [&](int kc, int stage) {
        int b = kc >> 6;
        int k0 = (kc & 63) * 32;
        const __nv_bfloat16* Ap = (b < 2) ? Ahi : Alo;
        const __nv_bfloat16* Bp = (b == 1) ? Blo : Bhi;
        uint32_t sb = sbase + stage * STAGEB;
#pragma unroll
        for (int it = 0; it < 4; it++) {
            int u = tid + it * 256;
            int row = (u >> 2) & 127;
            int chunk = u & 3;
            const __nv_bfloat16* src;
            uint32_t dst;
            if (u < 512) {
                src = Ap + (size_t)(tm + row) * GK + k0 + chunk * 8;
                dst = sb + row * ROWB + chunk * 16;
            } else {
                src = Bp + (size_t)(tn + row) * GK + k0 + chunk * 8;
                dst = sb + TILEB + row * ROWB + chunk * 16;
            }
            cpa16(dst, src);
        }
        asm volatile("cp.async.commit_group;" ::: "memory");
    };

    issue_load(0, 0);
    issue_load(1, 1);
    issue_load(2, 2);

    // ldmatrix lane addressing (derived from PTX fragment layouts)
    int arow_l = (lane & 7) + ((lane >> 3) & 1) * 8;   // A: row within 16
    int acol   = (lane >> 4) * 8;                      // A: k-half
    int brow_l = (lane & 7) + ((lane >> 4) & 1) * 8;   // B: n within 16
    int bcol   = ((lane >> 3) & 1) * 8;                // B: k-half

    for (int kc = 0; kc < NKC; kc++) {
        if (kc < NKC - 2)      asm volatile("cp.async.wait_group 2;" ::: "memory");
        else if (kc == NKC - 2) asm volatile("cp.async.wait_group 1;" ::: "memory");
        else                   asm volatile("cp.async.wait_group 0;" ::: "memory");
        __syncthreads();

        uint32_t sb = sbase + (kc & 3) * STAGEB;
#pragma unroll
        for (int ks = 0; ks < 2; ks++) {
            uint32_t a_regs[4][4];
#pragma unroll
            for (int i = 0; i < 4; i++)
                ldsm4(a_regs[i],
                      sb + (wm * 64 + i * 16 + arow_l) * ROWB + (ks * 16 + acol) * 2);
            uint32_t b_regs[2][4];
#pragma unroll
            for (int j = 0; j < 2; j++)
                ldsm4(b_regs[j],
                      sb + TILEB + (wn * 32 + j * 16 + brow_l) * ROWB + (ks * 16 + bcol) * 2);
#pragma unroll
            for (int i = 0; i < 4; i++)
#pragma unroll
                for (int jj = 0; jj < 4; jj++)
                    mma16816(acc[i][jj], a_regs[i],
                             b_regs[jj >> 1][(jj & 1) * 2],
                             b_regs[jj >> 1][(jj & 1) * 2 + 1]);
        }
        __syncthreads();
        if (kc + 3 < NKC) issue_load(kc + 3, (kc + 3) & 3);
    }

    // ---- epilogue: bias + activations from registers ----
    int g = lane >> 2, tg = lane & 3;
#pragma unroll
    for (int i = 0; i < 4; i++) {
        int row0 = tm + wm * 64 + i * 16 + g;
#pragma unroll
        for (int jj = 0; jj < 4; jj++) {
            int col = tn + wn * 32 + jj * 8 + tg * 2;
            float v0 = acc[i][jj][0], v1 = acc[i][jj][1];
            float v2 = acc[i][jj][2], v3 = acc[i][jj][3];
            if (bias) {
                float b0 = bias[col], b1 = bias[col + 1];
                v0 += b0; v1 += b1; v2 += b0; v3 += b1;
            }
            if (mode) {
                if (col < 2560) {
                    v0 = fmaxf(v0, 0.f); v1 = fmaxf(v1, 0.f);
                    v2 = fmaxf(v2, 0.f); v3 = fmaxf(v3, 0.f);
                    if (col < 2048) {
                        const float s = 0.08838834764831843f;
                        v0 *= s; v1 *= s; v2 *= s; v3 *= s;
                    }
                }
            }
            *(float2*)(C + (size_t)row0 * N + col)       = make_float2(v0, v1);
            *(float2*)(C + (size_t)(row0 + 8) * N + col) = make_float2(v2, v3);
        }
    }
}

// ---------------- gate low-rank projections -----------------------------------
__global__ void __launch_bounds__(256) gk1_kernel(const float* __restrict__ hidden,
                                                  const float* __restrict__ w0) {
    int t = blockIdx.x, tid = threadIdx.x;
    float acc[16];
#pragma unroll
    for (int r = 0; r < 16; r++) acc[r] = 0.f;
    const float* hrow = hidden + (size_t)t * H_;
    for (int h = tid; h < H_; h += 256) {
        float x = hrow[h];
        const float4* w = (const float4*)(w0 + (size_t)h * 16);
#pragma unroll
        for (int q = 0; q < 4; q++) {
            float4 w4 = w[q];
            acc[q * 4 + 0] += x * w4.x;
            acc[q * 4 + 1] += x * w4.y;
            acc[q * 4 + 2] += x * w4.z;
            acc[q * 4 + 3] += x * w4.w;
        }
    }
    __shared__ float sred[256][16];
#pragma unroll
    for (int r = 0; r < 16; r++) sred[tid][r] = acc[r];
    __syncthreads();
    if (tid < 16) {
        float s = 0.f;
        for (int i = 0; i < 256; i++) s += sred[i][tid];
        g_tmp16[(size_t)t * 16 + tid] = s;
    }
}

__global__ void __launch_bounds__(256) gk2_kernel(const float* __restrict__ w1,
                                                  const float* __restrict__ b1) {
    int idx = blockIdx.x * 256 + threadIdx.x;
    int t = idx >> 9, n = idx & 511;
    const float* tp = g_tmp16 + (size_t)t * 16;
    float x = b1[n];
#pragma unroll
    for (int r = 0; r < 16; r++) x += tp[r] * w1[r * 512 + n];
    float ls = (x >= 0.f) ? (-log1pf(expf(-x))) : (x - log1pf(expf(x)));
    g_g[(size_t)t * 512 + n] = ls * (1.f / 16.f);
}

// ---------------- per-chunk cumsum + pre-scale q~ / k~ in place ----------------
__global__ void __launch_bounds__(128) chunkB_kernel() {
    int c = blockIdx.x, kv = blockIdx.y, d = threadIdx.x;
    float cum = 0.f;
    for (int t = 0; t < CH; t++) {
        size_t tg = (size_t)c * CH + t;
        size_t gi = tg * 512 + kv * 128 + d;
        cum += g_g[gi];
        g_B[gi] = cum;
        float eB = expf(cum), eBn = expf(-cum);
        size_t rb = tg * QKVW;
        g_qkv[rb + 2048 + kv * 128 + d] *= eBn;
#pragma unroll
        for (int r = 0; r < 4; r++)
            g_qkv[rb + (kv * 4 + r) * 128 + d] *= eB;
    }
}

// ---------------- per-chunk increment P = exp(Btot) ⊙ (K~^T V) ----------------
__global__ void __launch_bounds__(256) chunkP_kernel() {
    __shared__ float sv[CH * 128];
    int c = blockIdx.x, kv = blockIdx.y, tid = threadIdx.x;
    for (int i = tid; i < CH * 32; i += 256) {
        int r = i >> 5, c4 = i & 31;
        ((float4*)sv)[i] = *(const float4*)(g_qkv + ((size_t)(c * CH + r)) * QKVW +
                                            2560 + kv * 128 + c4 * 4);
    }
    __syncthreads();
    int dk = tid >> 1, half = (tid & 1) * 64;
    float acc[64];
#pragma unroll
    for (int j = 0; j < 64; j++) acc[j] = 0.f;
    for (int t = 0; t < CH; t++) {
        float kk = g_qkv[((size_t)(c * CH + t)) * QKVW + 2048 + kv * 128 + dk];
        const float* vr = sv + t * 128 + half;
#pragma unroll
        for (int j = 0; j < 64; j++) acc[j] += kk * vr[j];
    }
    float eb = expf(g_B[((size_t)(c * CH + CH - 1)) * 512 + kv * 128 + dk]);
    float* pp = g_P + (((size_t)(c * 4 + kv)) * 128 + dk) * 128 + half;
#pragma unroll
    for (int j = 0; j < 64; j++) pp[j] = acc[j] * eb;
}

// ---------------- sequential inter-chunk combine -------------------------------
__global__ void __launch_bounds__(256) combine_kernel() {
    int kv = blockIdx.x >> 2, slice = blockIdx.x & 3;
    int tid = threadIdx.x;
    int dvl = tid & 31, dkg = tid >> 5;
    float S[16];
#pragma unroll
    for (int i = 0; i < 16; i++) S[i] = 0.f;
    for (int c = 0; c < NC; c++) {
        size_t base = ((size_t)(c * 4 + kv)) * 128 * 128;
        const float* Bt = g_B + ((size_t)(c * CH + CH - 1)) * 512 + kv * 128;
#pragma unroll
        for (int i = 0; i < 16; i++) {
            int dk = dkg * 16 + i;
            size_t idx = base + (size_t)dk * 128 + slice * 32 + dvl;
            g_S[idx] = S[i];
            float eb = expf(Bt[dk]);
            S[i] = eb * S[i] + g_P[idx];
        }
    }
}

// ---------------- intra-chunk output + RMSNorm --------------------------------
__global__ void __launch_bounds__(256) out_kernel(const float* __restrict__ gnw) {
    __shared__ float sK[CH * 128];
    __shared__ float sA[CH * CH];
    int c = blockIdx.x, h = blockIdx.y, kv = h >> 2;
    int tid = threadIdx.x;
    const float* qb = g_qkv + (size_t)c * CH * QKVW + h * 128;
    const float* kb = g_qkv + (size_t)c * CH * QKVW + 2048 + kv * 128;
    const float* vb = g_qkv + (size_t)c * CH * QKVW + 2560 + kv * 128;

    for (int i = tid; i < CH * 32; i += 256) {
        int r = i >> 5, c4 = i & 31;
        ((float4*)sK)[i] = *(const float4*)(kb + (size_t)r * QKVW + c4 * 4);
    }
    __syncthreads();

    {
        int t = tid >> 2, sq = (tid & 3) << 4;
        float a[16];
#pragma unroll
        for (int j = 0; j < 16; j++) a[j] = 0.f;
        const float* qr = qb + (size_t)t * QKVW;
        for (int dk = 0; dk < 128; dk++) {
            float qv = __ldg(qr + dk);
#pragma unroll
            for (int j = 0; j < 16; j++) a[j] += qv * sK[(sq + j) * 128 + dk];
        }
#pragma unroll
        for (int j = 0; j < 16; j++)
            sA[t * CH + sq + j] = (sq + j <= t) ? a[j] : 0.f;
    }
    __syncthreads();

    const float* Sb = g_S + ((size_t)(c * 4 + kv)) * 128 * 128;
    int t = tid >> 2, dq = (tid & 3) << 5;
    float acc[32];
#pragma unroll
    for (int j = 0; j < 32; j++) acc[j] = 0.f;
    const float* qr = qb + (size_t)t * QKVW;
    for (int dk = 0; dk < 128; dk++) {
        float qv = __ldg(qr + dk);
        const float4* s4 = (const float4*)(Sb + (size_t)dk * 128 + dq);
#pragma unroll
        for (int j4 = 0; j4 < 8; j4++) {
            float4 s = __ldg(s4 + j4);
            acc[j4 * 4 + 0] += qv * s.x;
            acc[j4 * 4 + 1] += qv * s.y;
            acc[j4 * 4 + 2] += qv * s.z;
            acc[j4 * 4 + 3] += qv * s.w;
        }
    }
    for (int s = 0; s < CH; s++) {
        float a = sA[t * CH + s];
        const float4* v4 = (const float4*)(vb + (size_t)s * QKVW + dq);
#pragma unroll
        for (int j4 = 0; j4 < 8; j4++) {
            float4 v = __ldg(v4 + j4);
            acc[j4 * 4 + 0] += a * v.x;
            acc[j4 * 4 + 1] += a * v.y;
            acc[j4 * 4 + 2] += a * v.z;
            acc[j4 * 4 + 3] += a * v.w;
        }
    }
    float ss = 0.f;
#pragma unroll
    for (int j = 0; j < 32; j++) ss += acc[j] * acc[j];
    ss += __shfl_xor_sync(0xffffffffu, ss, 1);
    ss += __shfl_xor_sync(0xffffffffu, ss, 2);
    float rn = rsqrtf(ss * (1.f / 128.f) + 1e-6f);
    size_t tg = (size_t)c * CH + t;
    float* orow = g_o + tg * 2048 + h * 128 + dq;
#pragma unroll
    for (int j = 0; j < 32; j++) orow[j] = acc[j] * rn * __ldg(gnw + dq + j);
}

// ---------------- launch -------------------------------------------------------
extern "C" void kernel_launch(void* const* d_in, const int* in_sizes, int n_in,
                              void* d_out, int out_size) {
    const float* hidden = (const float*)d_in[0];
    const float* Wqkv   = (const float*)d_in[1];
    const float* bqkv   = (const float*)d_in[2];
    const float* gk_w0  = (const float*)d_in[3];
    const float* gk_w1  = (const float*)d_in[4];
    const float* gk_b1  = (const float*)d_in[5];
    const float* gnormw = (const float*)d_in[6];
    const float* Wo     = (const float*)d_in[7];
    float* out = (float*)d_out;

    float *p_qkv, *p_o;
    __nv_bfloat16 *p_hAhi, *p_hAlo, *p_Wqhi, *p_Wqlo, *p_Wohi, *p_Wolo, *p_oAhi, *p_oAlo;
    cudaGetSymbolAddress((void**)&p_qkv, g_qkv);
    cudaGetSymbolAddress((void**)&p_o, g_o);
    cudaGetSymbolAddress((void**)&p_hAhi, g_hAhi);
    cudaGetSymbolAddress((void**)&p_hAlo, g_hAlo);
    cudaGetSymbolAddress((void**)&p_Wqhi, g_Wqhi);
    cudaGetSymbolAddress((void**)&p_Wqlo, g_Wqlo);
    cudaGetSymbolAddress((void**)&p_Wohi, g_Wohi);
    cudaGetSymbolAddress((void**)&p_Wolo, g_Wolo);
    cudaGetSymbolAddress((void**)&p_oAhi, g_oAhi);
    cudaGetSymbolAddress((void**)&p_oAlo, g_oAlo);

    cudaFuncSetAttribute(gemm_mma, cudaFuncAttributeMaxDynamicSharedMemorySize, GSMEM);

    // operand prep
    split_kernel<<<(T_ * H_) / 256, 256>>>(hidden, p_hAhi, p_hAlo);
    wsplit_kernel<<<dim3(QKVW / 32, GK / 32), 256>>>(Wqkv, p_Wqhi, p_Wqlo, QKVW);
    wsplit_kernel<<<dim3(H_ / 32, GK / 32), 256>>>(Wo, p_Wohi, p_Wolo, H_);

    // 1) qkv = hidden @ Wqkv + bias, fused relu/scale epilogue
    gemm_mma<<<dim3(QKVW / 128, T_ / 128), 256, GSMEM>>>(
        p_hAhi, p_hAlo, p_Wqhi, p_Wqlo, bqkv, p_qkv, QKVW, 1);

    // 2) gate projections
    gk1_kernel<<<T_, 256>>>(hidden, gk_w0);
    gk2_kernel<<<(T_ * 512) / 256, 256>>>(gk_w1, gk_b1);

    // 3) chunked GLA
    chunkB_kernel<<<dim3(NC, NKV_), 128>>>();
    chunkP_kernel<<<dim3(NC, NKV_), 256>>>();
    combine_kernel<<<16, 256>>>();
    out_kernel<<<dim3(NC, NH_), 256>>>(gnormw);

    // 4) o_proj = g_o @ Wo
    split_kernel<<<(T_ * H_) / 256, 256>>>(p_o, p_oAhi, p_oAlo);
    gemm_mma<<<dim3(H_ / 128, T_ / 128), 256, GSMEM>>>(
        p_oAhi, p_oAlo, p_Wohi, p_Wolo, nullptr, out, H_, 0);
}

// round 4
// speedup vs baseline: 3.4569x; 2.1954x over previous
#include <cuda_runtime.h>
#include <cuda_fp16.h>
#include <cstdint>
#include <math.h>

#define T_   8192
#define H_   2048
#define NH_  16
#define NKV_ 4
#define D_   128
#define CH   64
#define NC   128          // T_/CH
#define QKVW 3072         // (NH + 2*NKV)*D
#define GK   2048         // true K of both big GEMMs
#define NKC2 128          // K_ext/32 = 2*2048/32

// ---------------- scratch (static device memory; no allocs allowed) ----------
__device__ __align__(256) float g_qkv[(size_t)T_ * QKVW];
__device__ __align__(256) float g_tmp16[(size_t)T_ * 16];
__device__ __align__(256) float g_g[(size_t)T_ * 512];
__device__ __align__(256) float g_EB[(size_t)NC * NKV_ * D_];   // exp(B_total) per chunk
__device__ __align__(256) float g_P[(size_t)NC * NKV_ * D_ * D_];
__device__ __align__(256) float g_S[(size_t)NC * NKV_ * D_ * D_];
__device__ __align__(256) float g_o[(size_t)T_ * 2048];
// fp16 operands for tensor-core GEMMs
__device__ __align__(256) __half g_hA16[(size_t)T_ * H_];
__device__ __align__(256) __half g_Wqhi[(size_t)QKVW * GK];   // [N,K]
__device__ __align__(256) __half g_Wqlo[(size_t)QKVW * GK];
__device__ __align__(256) __half g_Wohi[(size_t)H_ * GK];     // [N,K]
__device__ __align__(256) __half g_Wolo[(size_t)H_ * GK];
__device__ __align__(256) __half g_oA16[(size_t)T_ * H_];

// ======================= small PTX helpers ====================================
__device__ __forceinline__ uint32_t smem_u32(const void* p) {
    uint32_t a;
    asm("{ .reg .u64 t; cvta.to.shared.u64 t, %1; cvt.u32.u64 %0, t; }" : "=r"(a) : "l"(p));
    return a;
}
__device__ __forceinline__ void cpa16(uint32_t dst, const void* src) {
    asm volatile("cp.async.cg.shared.global [%0], [%1], 16;" :: "r"(dst), "l"(src));
}
__device__ __forceinline__ void ldsm4(uint32_t* r, uint32_t addr) {
    asm volatile("ldmatrix.sync.aligned.m8n8.x4.shared.b16 {%0,%1,%2,%3}, [%4];"
                 : "=r"(r[0]), "=r"(r[1]), "=r"(r[2]), "=r"(r[3]) : "r"(addr));
}
__device__ __forceinline__ void mma16816(float* d, const uint32_t* a,
                                         uint32_t b0, uint32_t b1) {
    asm volatile("mma.sync.aligned.m16n8k16.row.col.f32.f16.f16.f32 "
                 "{%0,%1,%2,%3}, {%4,%5,%6,%7}, {%8,%9}, {%0,%1,%2,%3};"
                 : "+f"(d[0]), "+f"(d[1]), "+f"(d[2]), "+f"(d[3])
                 : "r"(a[0]), "r"(a[1]), "r"(a[2]), "r"(a[3]), "r"(b0), "r"(b1));
}

// ======================= fp32 -> fp16 conversions =============================
__global__ void __launch_bounds__(256) splitA16(const float* __restrict__ src,
                                                __half* __restrict__ dst) {
    size_t i4 = ((size_t)blockIdx.x * 256 + threadIdx.x) * 4;
    float4 v = *(const float4*)(src + i4);
    __half2* d = (__half2*)(dst + i4);
    d[0] = __floats2half2_rn(v.x, v.y);
    d[1] = __floats2half2_rn(v.z, v.w);
}

// W [K=2048, N] row-major fp32 -> hi/lo fp16 [N, K=2048]
__global__ void __launch_bounds__(256) wsplit16(const float* __restrict__ W,
                                                __half* __restrict__ hi,
                                                __half* __restrict__ lo, int N) {
    __shared__ float t[32][33];
    int bx = blockIdx.x, by = blockIdx.y;
    int lx = threadIdx.x & 31, ly = threadIdx.x >> 5;
    for (int r = ly; r < 32; r += 8)
        t[r][lx] = W[(size_t)(by * 32 + r) * N + bx * 32 + lx];
    __syncthreads();
    for (int r = ly; r < 32; r += 8) {
        float x = t[lx][r];
        __half h = __float2half_rn(x);
        size_t idx = (size_t)(bx * 32 + r) * GK + by * 32 + lx;
        hi[idx] = h;
        lo[idx] = __float2half_rn(x - __half2float(h));
    }
}

// ======================= HMMA GEMM (fp16 2-pass) ==============================
// C[M,N] = A16@Bhi^T + A16@Blo^T  via K_ext = 2*2048.
// CTA tile 128x128, 8 warps (warp tile 64x32), K-chunk 32, 4-stage cp.async.
#define ROWB   80
#define TILEB  (128 * ROWB)
#define STAGEB (2 * TILEB)
#define GSMEM  (4 * STAGEB)      // 81920

__global__ void __launch_bounds__(256) gemm_mma(
    const __half* __restrict__ A16,
    const __half* __restrict__ Bhi, const __half* __restrict__ Blo,
    const float* __restrict__ bias, float* __restrict__ C, int N, int mode) {
    extern __shared__ char smraw[];
    uint32_t sbase = smem_u32(smraw);
    int tid = threadIdx.x, wid = tid >> 5, lane = tid & 31;
    int tm = blockIdx.y * 128, tn = blockIdx.x * 128;
    int wm = wid & 1, wn = wid >> 1;

    float acc[4][4][4];
#pragma unroll
    for (int i = 0; i < 4; i++)
#pragma unroll
        for (int j = 0; j < 4; j++)
#pragma unroll
            for (int r = 0; r < 4; r++) acc[i][j][r] = 0.f;

    auto issue_load = [&](int kc, int stage) {
        const __half* Bp = (kc >= 64) ? Blo : Bhi;
        int k0 = (kc & 63) * 32;
        uint32_t sb = sbase + stage * STAGEB;
#pragma unroll
        for (int it = 0; it < 4; it++) {
            int u = tid + it * 256;
            int row = (u >> 2) & 127;
            int chunk = u & 3;
            const __half* src;
            uint32_t dst;
            if (u < 512) {
                src = A16 + (size_t)(tm + row) * GK + k0 + chunk * 8;
                dst = sb + row * ROWB + chunk * 16;
            } else {
                src = Bp + (size_t)(tn + row) * GK + k0 + chunk * 8;
                dst = sb + TILEB + row * ROWB + chunk * 16;
            }
            cpa16(dst, src);
        }
        asm volatile("cp.async.commit_group;" ::: "memory");
    };

    issue_load(0, 0);
    issue_load(1, 1);
    issue_load(2, 2);

    int arow_l = (lane & 7) + ((lane >> 3) & 1) * 8;
    int acol   = (lane >> 4) * 8;
    int brow_l = (lane & 7) + ((lane >> 4) & 1) * 8;
    int bcol   = ((lane >> 3) & 1) * 8;

    for (int kc = 0; kc < NKC2; kc++) {
        if (kc < NKC2 - 2)       asm volatile("cp.async.wait_group 2;" ::: "memory");
        else if (kc == NKC2 - 2) asm volatile("cp.async.wait_group 1;" ::: "memory");
        else                     asm volatile("cp.async.wait_group 0;" ::: "memory");
        __syncthreads();

        uint32_t sb = sbase + (kc & 3) * STAGEB;
#pragma unroll
        for (int ks = 0; ks < 2; ks++) {
            uint32_t a_regs[4][4];
#pragma unroll
            for (int i = 0; i < 4; i++)
                ldsm4(a_regs[i],
                      sb + (wm * 64 + i * 16 + arow_l) * ROWB + (ks * 16 + acol) * 2);
            uint32_t b_regs[2][4];
#pragma unroll
            for (int j = 0; j < 2; j++)
                ldsm4(b_regs[j],
                      sb + TILEB + (wn * 32 + j * 16 + brow_l) * ROWB + (ks * 16 + bcol) * 2);
#pragma unroll
            for (int i = 0; i < 4; i++)
#pragma unroll
                for (int jj = 0; jj < 4; jj++)
                    mma16816(acc[i][jj], a_regs[i],
                             b_regs[jj >> 1][(jj & 1) * 2],
                             b_regs[jj >> 1][(jj & 1) * 2 + 1]);
        }
        __syncthreads();
        if (kc + 3 < NKC2) issue_load(kc + 3, (kc + 3) & 3);
    }

    int g = lane >> 2, tg = lane & 3;
#pragma unroll
    for (int i = 0; i < 4; i++) {
        int row0 = tm + wm * 64 + i * 16 + g;
#pragma unroll
        for (int jj = 0; jj < 4; jj++) {
            int col = tn + wn * 32 + jj * 8 + tg * 2;
            float v0 = acc[i][jj][0], v1 = acc[i][jj][1];
            float v2 = acc[i][jj][2], v3 = acc[i][jj][3];
            if (bias) {
                float b0 = bias[col], b1 = bias[col + 1];
                v0 += b0; v1 += b1; v2 += b0; v3 += b1;
            }
            if (mode) {
                if (col < 2560) {
                    v0 = fmaxf(v0, 0.f); v1 = fmaxf(v1, 0.f);
                    v2 = fmaxf(v2, 0.f); v3 = fmaxf(v3, 0.f);
                    if (col < 2048) {
                        const float s = 0.08838834764831843f;
                        v0 *= s; v1 *= s; v2 *= s; v3 *= s;
                    }
                }
            }
            *(float2*)(C + (size_t)row0 * N + col)       = make_float2(v0, v1);
            *(float2*)(C + (size_t)(row0 + 8) * N + col) = make_float2(v2, v3);
        }
    }
}

// ---------------- gate low-rank projections -----------------------------------
__global__ void __launch_bounds__(256) gk1_kernel(const float* __restrict__ hidden,
                                                  const float* __restrict__ w0) {
    int t = blockIdx.x, tid = threadIdx.x;
    float acc[16];
#pragma unroll
    for (int r = 0; r < 16; r++) acc[r] = 0.f;
    const float* hrow = hidden + (size_t)t * H_;
    for (int h = tid; h < H_; h += 256) {
        float x = hrow[h];
        const float4* w = (const float4*)(w0 + (size_t)h * 16);
#pragma unroll
        for (int q = 0; q < 4; q++) {
            float4 w4 = w[q];
            acc[q * 4 + 0] += x * w4.x;
            acc[q * 4 + 1] += x * w4.y;
            acc[q * 4 + 2] += x * w4.z;
            acc[q * 4 + 3] += x * w4.w;
        }
    }
    __shared__ float sred[256][16];
#pragma unroll
    for (int r = 0; r < 16; r++) sred[tid][r] = acc[r];
    __syncthreads();
    if (tid < 16) {
        float s = 0.f;
        for (int i = 0; i < 256; i++) s += sred[i][tid];
        g_tmp16[(size_t)t * 16 + tid] = s;
    }
}

__global__ void __launch_bounds__(256) gk2_kernel(const float* __restrict__ w1,
                                                  const float* __restrict__ b1) {
    int idx = blockIdx.x * 256 + threadIdx.x;
    int t = idx >> 9, n = idx & 511;
    const float* tp = g_tmp16 + (size_t)t * 16;
    float x = b1[n];
#pragma unroll
    for (int r = 0; r < 16; r++) x += tp[r] * w1[r * 512 + n];
    float ls = (x >= 0.f) ? (-log1pf(expf(-x))) : (x - log1pf(expf(x)));
    g_g[(size_t)t * 512 + n] = ls * (1.f / 16.f);
}

// ---------------- per-chunk cumsum + pre-scale q~ / k~ in place ----------------
__global__ void __launch_bounds__(128) chunkB_kernel() {
    int c = blockIdx.x, kv = blockIdx.y, d = threadIdx.x;
    float cum = 0.f;
    for (int t = 0; t < CH; t++) {
        size_t tg = (size_t)c * CH + t;
        cum += g_g[tg * 512 + kv * 128 + d];
        float eB = expf(cum), eBn = expf(-cum);
        size_t rb = tg * QKVW;
        g_qkv[rb + 2048 + kv * 128 + d] *= eBn;
#pragma unroll
        for (int r = 0; r < 4; r++)
            g_qkv[rb + (kv * 4 + r) * 128 + d] *= eB;
    }
    g_EB[(size_t)(c * 4 + kv) * 128 + d] = expf(cum);
}

// ---------------- per-chunk increment P = exp(Btot) ⊙ (K~^T V) ----------------
__global__ void __launch_bounds__(256) chunkP_kernel() {
    __shared__ float sv[CH * 128];
    int c = blockIdx.x, kv = blockIdx.y, tid = threadIdx.x;
    for (int i = tid; i < CH * 32; i += 256) {
        int r = i >> 5, c4 = i & 31;
        ((float4*)sv)[i] = *(const float4*)(g_qkv + ((size_t)(c * CH + r)) * QKVW +
                                            2560 + kv * 128 + c4 * 4);
    }
    __syncthreads();
    int dk = tid >> 1, half = (tid & 1) * 64;
    float4 acc[16];
#pragma unroll
    for (int j = 0; j < 16; j++) acc[j] = make_float4(0.f, 0.f, 0.f, 0.f);
    for (int t = 0; t < CH; t++) {
        float kk = g_qkv[((size_t)(c * CH + t)) * QKVW + 2048 + kv * 128 + dk];
        const float4* vr = (const float4*)(sv + t * 128 + half);
#pragma unroll
        for (int j = 0; j < 16; j++) {
            float4 v = vr[j];
            acc[j].x += kk * v.x; acc[j].y += kk * v.y;
            acc[j].z += kk * v.z; acc[j].w += kk * v.w;
        }
    }
    float eb = g_EB[(size_t)(c * 4 + kv) * 128 + dk];
    float4* pp = (float4*)(g_P + (((size_t)(c * 4 + kv)) * 128 + dk) * 128 + half);
#pragma unroll
    for (int j = 0; j < 16; j++) {
        float4 v = acc[j];
        v.x *= eb; v.y *= eb; v.z *= eb; v.w *= eb;
        pp[j] = v;
    }
}

// ---------------- inter-chunk combine: element-parallel scan -------------------
__global__ void __launch_bounds__(256) combine_kernel() {
    int g = blockIdx.x * 256 + threadIdx.x;     // 65536 threads
    int dv = g & 127, dk = (g >> 7) & 127, kv = g >> 14;
    float s = 0.f;
    for (int c = 0; c < NC; c++) {
        size_t idx = ((size_t)(c * 4 + kv) * 128 + dk) * 128 + dv;
        g_S[idx] = s;
        float eb = g_EB[(size_t)(c * 4 + kv) * 128 + dk];
        s = eb * s + g_P[idx];
    }
}

// ---------------- intra-chunk output + RMSNorm --------------------------------
// dynamic smem: sQ[64][132] | union(sKT[128][68], sV[64][132]) | sA[64][65]
#define OQ_STR 132
#define OK_STR 68
#define OA_STR 65
#define O_SQ   0
#define O_KT   (64 * OQ_STR)
#define O_SA   (O_KT + 128 * OK_STR)
#define OSMEM  ((O_SA + 64 * OA_STR) * 4)

__global__ void __launch_bounds__(256) out_kernel(const float* __restrict__ gnw) {
    extern __shared__ float sm[];
    float* sQ  = sm + O_SQ;
    float* sKT = sm + O_KT;
    float* sV  = sm + O_KT;
    float* sA  = sm + O_SA;
    int c = blockIdx.x, h = blockIdx.y, kv = h >> 2;
    int tid = threadIdx.x;
    const float* qb = g_qkv + (size_t)c * CH * QKVW + h * 128;
    const float* kb = g_qkv + (size_t)c * CH * QKVW + 2048 + kv * 128;
    const float* vb = g_qkv + (size_t)c * CH * QKVW + 2560 + kv * 128;

    // fill sQ (row-major) and sKT (transposed)
#pragma unroll
    for (int it = 0; it < 8; it++) {
        int u = tid + it * 256;
        int r = u >> 5, c4 = (u & 31) * 4;
        *(float4*)(sQ + r * OQ_STR + c4) = *(const float4*)(qb + (size_t)r * QKVW + c4);
        float4 kvv = *(const float4*)(kb + (size_t)r * QKVW + c4);
        sKT[(c4 + 0) * OK_STR + r] = kvv.x;
        sKT[(c4 + 1) * OK_STR + r] = kvv.y;
        sKT[(c4 + 2) * OK_STR + r] = kvv.z;
        sKT[(c4 + 3) * OK_STR + r] = kvv.w;
    }
    __syncthreads();

    int tt = tid >> 4, sg = tid & 15;
    int t0 = tt * 4, s0 = sg * 4;

    // phase 1: A = Q~ K~^T with causal mask, 4x4 register tile
    {
        float a[4][4];
#pragma unroll
        for (int i = 0; i < 4; i++)
#pragma unroll
            for (int j = 0; j < 4; j++) a[i][j] = 0.f;
        for (int dk = 0; dk < 128; dk++) {
            float4 kx = *(const float4*)(sKT + dk * OK_STR + s0);
#pragma unroll
            for (int i = 0; i < 4; i++) {
                float q = sQ[(t0 + i) * OQ_STR + dk];
                a[i][0] += q * kx.x; a[i][1] += q * kx.y;
                a[i][2] += q * kx.z; a[i][3] += q * kx.w;
            }
        }
#pragma unroll
        for (int i = 0; i < 4; i++)
#pragma unroll
            for (int j = 0; j < 4; j++)
                sA[(t0 + i) * OA_STR + s0 + j] = (s0 + j <= t0 + i) ? a[i][j] : 0.f;
    }
    __syncthreads();

    // fill sV (overwrites sKT region)
#pragma unroll
    for (int it = 0; it < 8; it++) {
        int u = tid + it * 256;
        int r = u >> 5, c4 = (u & 31) * 4;
        *(float4*)(sV + r * OQ_STR + c4) = *(const float4*)(vb + (size_t)r * QKVW + c4);
    }
    __syncthreads();

    // phase 2: o = Q~ S + A V, thread = (t-group of 4, dv-group of 8)
    int dq0 = sg * 8;
    float acc[4][8];
#pragma unroll
    for (int i = 0; i < 4; i++)
#pragma unroll
        for (int j = 0; j < 8; j++) acc[i][j] = 0.f;

    const float* Sb = g_S + (size_t)(c * 4 + kv) * 16384;
    for (int dk = 0; dk < 128; dk++) {
        float4 s0v = __ldg((const float4*)(Sb + dk * 128 + dq0));
        float4 s1v = __ldg((const float4*)(Sb + dk * 128 + dq0 + 4));
#pragma unroll
        for (int i = 0; i < 4; i++) {
            float q = sQ[(t0 + i) * OQ_STR + dk];
            acc[i][0] += q * s0v.x; acc[i][1] += q * s0v.y;
            acc[i][2] += q * s0v.z; acc[i][3] += q * s0v.w;
            acc[i][4] += q * s1v.x; acc[i][5] += q * s1v.y;
            acc[i][6] += q * s1v.z; acc[i][7] += q * s1v.w;
        }
    }
    for (int s = 0; s < CH; s++) {
        float4 v0 = *(const float4*)(sV + s * OQ_STR + dq0);
        float4 v1 = *(const float4*)(sV + s * OQ_STR + dq0 + 4);
#pragma unroll
        for (int i = 0; i < 4; i++) {
            float av = sA[(t0 + i) * OA_STR + s];
            acc[i][0] += av * v0.x; acc[i][1] += av * v0.y;
            acc[i][2] += av * v0.z; acc[i][3] += av * v0.w;
            acc[i][4] += av * v1.x; acc[i][5] += av * v1.y;
            acc[i][6] += av * v1.z; acc[i][7] += av * v1.w;
        }
    }

    // fused RMSNorm: reduce over 16 dv-group lanes (dq covers 128 via 16 threads)
#pragma unroll
    for (int i = 0; i < 4; i++) {
        float ssum = 0.f;
#pragma unroll
        for (int j = 0; j < 8; j++) ssum += acc[i][j] * acc[i][j];
#pragma unroll
        for (int m = 1; m < 16; m <<= 1)
            ssum += __shfl_xor_sync(0xffffffffu, ssum, m);
        float rn = rsqrtf(ssum * (1.f / 128.f) + 1e-6f);
        float* orow = g_o + ((size_t)(c * CH) + t0 + i) * 2048 + h * 128 + dq0;
#pragma unroll
        for (int j = 0; j < 8; j++) orow[j] = acc[i][j] * rn * __ldg(gnw + dq0 + j);
    }
}

// ---------------- launch -------------------------------------------------------
extern "C" void kernel_launch(void* const* d_in, const int* in_sizes, int n_in,
                              void* d_out, int out_size) {
    const float* hidden = (const float*)d_in[0];
    const float* Wqkv   = (const float*)d_in[1];
    const float* bqkv   = (const float*)d_in[2];
    const float* gk_w0  = (const float*)d_in[3];
    const float* gk_w1  = (const float*)d_in[4];
    const float* gk_b1  = (const float*)d_in[5];
    const float* gnormw = (const float*)d_in[6];
    const float* Wo     = (const float*)d_in[7];
    float* out = (float*)d_out;

    float *p_qkv, *p_o;
    __half *p_hA16, *p_Wqhi, *p_Wqlo, *p_Wohi, *p_Wolo, *p_oA16;
    cudaGetSymbolAddress((void**)&p_qkv, g_qkv);
    cudaGetSymbolAddress((void**)&p_o, g_o);
    cudaGetSymbolAddress((void**)&p_hA16, g_hA16);
    cudaGetSymbolAddress((void**)&p_Wqhi, g_Wqhi);
    cudaGetSymbolAddress((void**)&p_Wqlo, g_Wqlo);
    cudaGetSymbolAddress((void**)&p_Wohi, g_Wohi);
    cudaGetSymbolAddress((void**)&p_Wolo, g_Wolo);
    cudaGetSymbolAddress((void**)&p_oA16, g_oA16);

    cudaFuncSetAttribute(gemm_mma, cudaFuncAttributeMaxDynamicSharedMemorySize, GSMEM);
    cudaFuncSetAttribute(out_kernel, cudaFuncAttributeMaxDynamicSharedMemorySize, OSMEM);

    // operand prep
    splitA16<<<(T_ * H_) / 1024, 256>>>(hidden, p_hA16);
    wsplit16<<<dim3(QKVW / 32, GK / 32), 256>>>(Wqkv, p_Wqhi, p_Wqlo, QKVW);
    wsplit16<<<dim3(H_ / 32, GK / 32), 256>>>(Wo, p_Wohi, p_Wolo, H_);

    // 1) qkv = hidden @ Wqkv + bias, fused relu/scale epilogue
    gemm_mma<<<dim3(QKVW / 128, T_ / 128), 256, GSMEM>>>(
        p_hA16, p_Wqhi, p_Wqlo, bqkv, p_qkv, QKVW, 1);

    // 2) gate projections
    gk1_kernel<<<T_, 256>>>(hidden, gk_w0);
    gk2_kernel<<<(T_ * 512) / 256, 256>>>(gk_w1, gk_b1);

    // 3) chunked GLA
    chunkB_kernel<<<dim3(NC, NKV_), 128>>>();
    chunkP_kernel<<<dim3(NC, NKV_), 256>>>();
    combine_kernel<<<256, 256>>>();
    out_kernel<<<dim3(NC, NH_), 256, OSMEM>>>(gnormw);

    // 4) o_proj = g_o @ Wo
    splitA16<<<(T_ * H_) / 1024, 256>>>(p_o, p_oA16);
    gemm_mma<<<dim3(H_ / 128, T_ / 128), 256, GSMEM>>>(
        p_oA16, p_Wohi, p_Wolo, nullptr, out, H_, 0);
}

// round 5
// speedup vs baseline: 4.1429x; 1.1984x over previous
#include <cuda_runtime.h>
#include <cuda_fp16.h>
#include <cstdint>
#include <math.h>

#define T_   8192
#define H_   2048
#define NH_  16
#define NKV_ 4
#define D_   128
#define CH   64
#define NC   128          // T_/CH
#define QKVW 3072
#define GK   2048

// ---------------- scratch (static device memory) ------------------------------
__device__ __align__(256) float g_qkv[(size_t)T_ * QKVW];
__device__ __align__(256) float g_tmp16[(size_t)T_ * 16];
__device__ __align__(256) float g_g[(size_t)T_ * 512];
__device__ __align__(256) float g_EB[(size_t)NC * NKV_ * D_];
__device__ __align__(256) float g_P[(size_t)NC * NKV_ * D_ * D_];
__device__ __align__(256) __half g_S16[(size_t)NC * NKV_ * D_ * D_];
// fp16 operands
__device__ __align__(256) __half g_hA16[(size_t)T_ * H_];
__device__ __align__(256) __half g_Wqhi[(size_t)QKVW * GK];
__device__ __align__(256) __half g_Wqlo[(size_t)QKVW * GK];
__device__ __align__(256) __half g_Wohi[(size_t)H_ * GK];
__device__ __align__(256) __half g_Wolo[(size_t)H_ * GK];
__device__ __align__(256) __half g_oA16[(size_t)T_ * H_];
__device__ __align__(256) __half g_q16[(size_t)T_ * 2048];   // q~ fp16
__device__ __align__(256) __half g_k16[(size_t)T_ * 512];    // k~ fp16
__device__ __align__(256) __half g_v16[(size_t)T_ * 512];    // v  fp16

// ======================= PTX helpers ==========================================
__device__ __forceinline__ uint32_t smem_u32(const void* p) {
    uint32_t a;
    asm("{ .reg .u64 t; cvta.to.shared.u64 t, %1; cvt.u32.u64 %0, t; }" : "=r"(a) : "l"(p));
    return a;
}
__device__ __forceinline__ void cpa16(uint32_t dst, const void* src) {
    asm volatile("cp.async.cg.shared.global [%0], [%1], 16;" :: "r"(dst), "l"(src));
}
__device__ __forceinline__ void ldsm4(uint32_t* r, uint32_t addr) {
    asm volatile("ldmatrix.sync.aligned.m8n8.x4.shared.b16 {%0,%1,%2,%3}, [%4];"
                 : "=r"(r[0]), "=r"(r[1]), "=r"(r[2]), "=r"(r[3]) : "r"(addr));
}
__device__ __forceinline__ void ldsm4t(uint32_t* r, uint32_t addr) {
    asm volatile("ldmatrix.sync.aligned.m8n8.x4.trans.shared.b16 {%0,%1,%2,%3}, [%4];"
                 : "=r"(r[0]), "=r"(r[1]), "=r"(r[2]), "=r"(r[3]) : "r"(addr));
}
__device__ __forceinline__ void mma16816(float* d, const uint32_t* a,
                                         uint32_t b0, uint32_t b1) {
    asm volatile("mma.sync.aligned.m16n8k16.row.col.f32.f16.f16.f32 "
                 "{%0,%1,%2,%3}, {%4,%5,%6,%7}, {%8,%9}, {%0,%1,%2,%3};"
                 : "+f"(d[0]), "+f"(d[1]), "+f"(d[2]), "+f"(d[3])
                 : "r"(a[0]), "r"(a[1]), "r"(a[2]), "r"(a[3]), "r"(b0), "r"(b1));
}

// ======================= conversions ==========================================
__global__ void __launch_bounds__(256) splitA16(const float* __restrict__ src,
                                                __half* __restrict__ dst) {
    size_t i4 = ((size_t)blockIdx.x * 256 + threadIdx.x) * 4;
    float4 v = *(const float4*)(src + i4);
    __half2* d = (__half2*)(dst + i4);
    d[0] = __floats2half2_rn(v.x, v.y);
    d[1] = __floats2half2_rn(v.z, v.w);
}

__global__ void __launch_bounds__(256) wsplit16(const float* __restrict__ W,
                                                __half* __restrict__ hi,
                                                __half* __restrict__ lo, int N) {
    __shared__ float t[32][33];
    int bx = blockIdx.x, by = blockIdx.y;
    int lx = threadIdx.x & 31, ly = threadIdx.x >> 5;
    for (int r = ly; r < 32; r += 8)
        t[r][lx] = W[(size_t)(by * 32 + r) * N + bx * 32 + lx];
    __syncthreads();
    for (int r = ly; r < 32; r += 8) {
        float x = t[lx][r];
        __half h = __float2half_rn(x);
        size_t idx = (size_t)(bx * 32 + r) * GK + by * 32 + lx;
        hi[idx] = h;
        lo[idx] = __float2half_rn(x - __half2float(h));
    }
}

// ======================= HMMA GEMM: shared-A, 2 B planes ======================
// C = A16 @ Bhi^T + A16 @ Blo^T. CTA 128x128, 8 warps, K-chunk 32, 3 stages.
#define ROWB   80
#define TILEB  (128 * ROWB)
#define STAGEB (3 * TILEB)       // A + Bhi + Blo
#define GSMEM  (3 * STAGEB)      // 92160

__global__ void __launch_bounds__(256) gemm_mma(
    const __half* __restrict__ A16,
    const __half* __restrict__ Bhi, const __half* __restrict__ Blo,
    const float* __restrict__ bias, float* __restrict__ C, int N, int mode) {
    extern __shared__ char smraw[];
    uint32_t sbase = smem_u32(smraw);
    int tid = threadIdx.x, wid = tid >> 5, lane = tid & 31;
    int tm = blockIdx.y * 128, tn = blockIdx.x * 128;
    int wm = wid & 1, wn = wid >> 1;

    float acc[4][4][4];
#pragma unroll
    for (int i = 0; i < 4; i++)
#pragma unroll
        for (int j = 0; j < 4; j++)
#pragma unroll
            for (int r = 0; r < 4; r++) acc[i][j][r] = 0.f;

    auto issue_load = [&](int k0i, int stage) {
        int k0 = k0i * 32;
        uint32_t sb = sbase + stage * STAGEB;
#pragma unroll
        for (int it = 0; it < 6; it++) {
            int u = tid + it * 256;
            int row = (u >> 2) & 127;
            int chunk = u & 3;
            const __half* src;
            uint32_t dst;
            if (u < 512) {
                src = A16 + (size_t)(tm + row) * GK + k0 + chunk * 8;
                dst = sb + row * ROWB + chunk * 16;
            } else if (u < 1024) {
                src = Bhi + (size_t)(tn + row) * GK + k0 + chunk * 8;
                dst = sb + TILEB + row * ROWB + chunk * 16;
            } else {
                src = Blo + (size_t)(tn + row) * GK + k0 + chunk * 8;
                dst = sb + 2 * TILEB + row * ROWB + chunk * 16;
            }
            cpa16(dst, src);
        }
        asm volatile("cp.async.commit_group;" ::: "memory");
    };

    issue_load(0, 0);
    issue_load(1, 1);
    issue_load(2, 2);

    int arow_l = (lane & 7) + ((lane >> 3) & 1) * 8;
    int acol   = (lane >> 4) * 8;
    int brow_l = (lane & 7) + ((lane >> 4) & 1) * 8;
    int bcol   = ((lane >> 3) & 1) * 8;

    for (int kc = 0; kc < 64; kc++) {
        if (kc < 62)       asm volatile("cp.async.wait_group 2;" ::: "memory");
        else if (kc == 62) asm volatile("cp.async.wait_group 1;" ::: "memory");
        else               asm volatile("cp.async.wait_group 0;" ::: "memory");
        __syncthreads();

        uint32_t sb = sbase + (kc % 3) * STAGEB;
#pragma unroll
        for (int ks = 0; ks < 2; ks++) {
            uint32_t a_regs[4][4];
#pragma unroll
            for (int i = 0; i < 4; i++)
                ldsm4(a_regs[i],
                      sb + (wm * 64 + i * 16 + arow_l) * ROWB + (ks * 16 + acol) * 2);
            uint32_t bh[2][4], bl[2][4];
#pragma unroll
            for (int j = 0; j < 2; j++) {
                ldsm4(bh[j], sb + TILEB +
                      (wn * 32 + j * 16 + brow_l) * ROWB + (ks * 16 + bcol) * 2);
                ldsm4(bl[j], sb + 2 * TILEB +
                      (wn * 32 + j * 16 + brow_l) * ROWB + (ks * 16 + bcol) * 2);
            }
#pragma unroll
            for (int i = 0; i < 4; i++)
#pragma unroll
                for (int jj = 0; jj < 4; jj++) {
                    mma16816(acc[i][jj], a_regs[i],
                             bh[jj >> 1][(jj & 1) * 2], bh[jj >> 1][(jj & 1) * 2 + 1]);
                    mma16816(acc[i][jj], a_regs[i],
                             bl[jj >> 1][(jj & 1) * 2], bl[jj >> 1][(jj & 1) * 2 + 1]);
                }
        }
        __syncthreads();
        if (kc + 3 < 64) issue_load(kc + 3, (kc + 3) % 3);
    }

    int g = lane >> 2, tg = lane & 3;
#pragma unroll
    for (int i = 0; i < 4; i++) {
        int row0 = tm + wm * 64 + i * 16 + g;
#pragma unroll
        for (int jj = 0; jj < 4; jj++) {
            int col = tn + wn * 32 + jj * 8 + tg * 2;
            float v0 = acc[i][jj][0], v1 = acc[i][jj][1];
            float v2 = acc[i][jj][2], v3 = acc[i][jj][3];
            if (bias) {
                float b0 = bias[col], b1 = bias[col + 1];
                v0 += b0; v1 += b1; v2 += b0; v3 += b1;
            }
            if (mode) {
                if (col < 2560) {
                    v0 = fmaxf(v0, 0.f); v1 = fmaxf(v1, 0.f);
                    v2 = fmaxf(v2, 0.f); v3 = fmaxf(v3, 0.f);
                    if (col < 2048) {
                        const float s = 0.08838834764831843f;
                        v0 *= s; v1 *= s; v2 *= s; v3 *= s;
                    }
                }
            }
            *(float2*)(C + (size_t)row0 * N + col)       = make_float2(v0, v1);
            *(float2*)(C + (size_t)(row0 + 8) * N + col) = make_float2(v2, v3);
        }
    }
}

// ---------------- gate low-rank projections -----------------------------------
__global__ void __launch_bounds__(256) gk1_kernel(const float* __restrict__ hidden,
                                                  const float* __restrict__ w0) {
    int t = blockIdx.x, tid = threadIdx.x;
    float acc[16];
#pragma unroll
    for (int r = 0; r < 16; r++) acc[r] = 0.f;
    const float* hrow = hidden + (size_t)t * H_;
    for (int h = tid; h < H_; h += 256) {
        float x = hrow[h];
        const float4* w = (const float4*)(w0 + (size_t)h * 16);
#pragma unroll
        for (int q = 0; q < 4; q++) {
            float4 w4 = w[q];
            acc[q * 4 + 0] += x * w4.x;
            acc[q * 4 + 1] += x * w4.y;
            acc[q * 4 + 2] += x * w4.z;
            acc[q * 4 + 3] += x * w4.w;
        }
    }
    __shared__ float sred[256][16];
#pragma unroll
    for (int r = 0; r < 16; r++) sred[tid][r] = acc[r];
    __syncthreads();
    if (tid < 16) {
        float s = 0.f;
        for (int i = 0; i < 256; i++) s += sred[i][tid];
        g_tmp16[(size_t)t * 16 + tid] = s;
    }
}

__global__ void __launch_bounds__(256) gk2_kernel(const float* __restrict__ w1,
                                                  const float* __restrict__ b1) {
    int idx = blockIdx.x * 256 + threadIdx.x;
    int t = idx >> 9, n = idx & 511;
    const float* tp = g_tmp16 + (size_t)t * 16;
    float x = b1[n];
#pragma unroll
    for (int r = 0; r < 16; r++) x += tp[r] * w1[r * 512 + n];
    float ls = (x >= 0.f) ? (-log1pf(expf(-x))) : (x - log1pf(expf(x)));
    g_g[(size_t)t * 512 + n] = ls * (1.f / 16.f);
}

// ---------------- per-chunk cumsum + fp16 operand emit -------------------------
__global__ void __launch_bounds__(128) chunkB_kernel() {
    int c = blockIdx.x, kv = blockIdx.y, d = threadIdx.x;
    float cum = 0.f;
    for (int t = 0; t < CH; t++) {
        size_t tg = (size_t)c * CH + t;
        cum += g_g[tg * 512 + kv * 128 + d];
        float eB = expf(cum), eBn = expf(-cum);
        size_t rb = tg * QKVW;
        g_k16[tg * 512 + kv * 128 + d] =
            __float2half_rn(g_qkv[rb + 2048 + kv * 128 + d] * eBn);
        g_v16[tg * 512 + kv * 128 + d] =
            __float2half_rn(g_qkv[rb + 2560 + kv * 128 + d]);
#pragma unroll
        for (int r = 0; r < 4; r++)
            g_q16[tg * 2048 + (kv * 4 + r) * 128 + d] =
                __float2half_rn(g_qkv[rb + (kv * 4 + r) * 128 + d] * eB);
    }
    g_EB[(size_t)(c * 4 + kv) * 128 + d] = expf(cum);
}

// ---------------- per-chunk increment P = exp(Btot) ⊙ (K~^T V) ----------------
__global__ void __launch_bounds__(256) chunkP_kernel() {
    __shared__ float sv[CH * 128];
    int c = blockIdx.x, kv = blockIdx.y, tid = threadIdx.x;
    for (int i = tid; i < CH * 64; i += 256) {
        int r = i >> 6, c2 = i & 63;
        __half2 hv = *(const __half2*)(g_v16 + ((size_t)(c * CH + r)) * 512 +
                                       kv * 128 + c2 * 2);
        float2 f = __half22float2(hv);
        sv[r * 128 + c2 * 2] = f.x;
        sv[r * 128 + c2 * 2 + 1] = f.y;
    }
    __syncthreads();
    int dk = tid >> 1, half = (tid & 1) * 64;
    float4 acc[16];
#pragma unroll
    for (int j = 0; j < 16; j++) acc[j] = make_float4(0.f, 0.f, 0.f, 0.f);
    for (int t = 0; t < CH; t++) {
        float kk = __half2float(g_k16[((size_t)(c * CH + t)) * 512 + kv * 128 + dk]);
        const float4* vr = (const float4*)(sv + t * 128 + half);
#pragma unroll
        for (int j = 0; j < 16; j++) {
            float4 v = vr[j];
            acc[j].x += kk * v.x; acc[j].y += kk * v.y;
            acc[j].z += kk * v.z; acc[j].w += kk * v.w;
        }
    }
    float eb = g_EB[(size_t)(c * 4 + kv) * 128 + dk];
    float4* pp = (float4*)(g_P + (((size_t)(c * 4 + kv)) * 128 + dk) * 128 + half);
#pragma unroll
    for (int j = 0; j < 16; j++) {
        float4 v = acc[j];
        v.x *= eb; v.y *= eb; v.z *= eb; v.w *= eb;
        pp[j] = v;
    }
}

// ---------------- inter-chunk combine: element-parallel, fp16 S out ------------
__global__ void __launch_bounds__(256) combine_kernel() {
    int g = blockIdx.x * 256 + threadIdx.x;
    int dv = g & 127, dk = (g >> 7) & 127, kv = g >> 14;
    float s = 0.f;
    for (int c = 0; c < NC; c++) {
        size_t idx = ((size_t)(c * 4 + kv) * 128 + dk) * 128 + dv;
        g_S16[idx] = __float2half_rn(s);
        float eb = g_EB[(size_t)(c * 4 + kv) * 128 + dk];
        s = eb * s + g_P[idx];
    }
}

// ---------------- intra-chunk output via mma + fused RMSNorm -------------------
// smem (bytes): Q[64x136h]@0, K@17408, V@34816, S[128x136h]@52224, A[64x72h]@87040
// O fp32 [64x132] aliases Q+K (offset 0). Total 96256.
#define OQ  0
#define OK  17408
#define OV  34816
#define OS  52224
#define OA  87040
#define OSMEM 96256

__global__ void __launch_bounds__(256) out_kernel(const float* __restrict__ gnw) {
    extern __shared__ char smraw[];
    uint32_t sb = smem_u32(smraw);
    float* sO = (float*)smraw;
    int c = blockIdx.x, h = blockIdx.y, kv = h >> 2;
    int tid = threadIdx.x, wid = tid >> 5, lane = tid & 31;
    int wm = wid >> 1, wn = wid & 1;

    // async load Q, K, V, S into smem
    {
        const __half* qg = g_q16 + (size_t)c * CH * 2048 + h * 128;
        const __half* kg = g_k16 + (size_t)c * CH * 512 + kv * 128;
        const __half* vg = g_v16 + (size_t)c * CH * 512 + kv * 128;
        const __half* sg = g_S16 + (size_t)(c * 4 + kv) * 16384;
        for (int u = tid; u < 5120; u += 256) {
            int r, ch;
            if (u < 1024) {
                r = u >> 4; ch = u & 15;
                cpa16(sb + OQ + r * 272 + ch * 16, qg + (size_t)r * 2048 + ch * 8);
            } else if (u < 2048) {
                int v = u - 1024; r = v >> 4; ch = v & 15;
                cpa16(sb + OK + r * 272 + ch * 16, kg + (size_t)r * 512 + ch * 8);
            } else if (u < 3072) {
                int v = u - 2048; r = v >> 4; ch = v & 15;
                cpa16(sb + OV + r * 272 + ch * 16, vg + (size_t)r * 512 + ch * 8);
            } else {
                int v = u - 3072; r = v >> 4; ch = v & 15;
                cpa16(sb + OS + r * 272 + ch * 16, sg + (size_t)r * 128 + ch * 8);
            }
        }
        asm volatile("cp.async.commit_group;" ::: "memory");
        asm volatile("cp.async.wait_group 0;" ::: "memory");
        __syncthreads();
    }

    int arow_l = (lane & 7) + ((lane >> 3) & 1) * 8;
    int acol   = (lane >> 4) * 8;
    int brow_l = (lane & 7) + ((lane >> 4) & 1) * 8;
    int bcol   = ((lane >> 3) & 1) * 8;
    int trow   = lane & 15;
    int tcol   = (lane >> 4) * 8;

    // phase 1: A = Q K^T (64x64), causal mask, -> sA fp16
    {
        float aacc[4][4];
#pragma unroll
        for (int i = 0; i < 4; i++)
#pragma unroll
            for (int j = 0; j < 4; j++) aacc[i][j] = 0.f;
#pragma unroll
        for (int kk = 0; kk < 8; kk++) {
            uint32_t ar[4];
            ldsm4(ar, sb + OQ + (wm * 16 + arow_l) * 272 + (kk * 16 + acol) * 2);
            uint32_t br[2][4];
#pragma unroll
            for (int j = 0; j < 2; j++)
                ldsm4(br[j], sb + OK + (wn * 32 + j * 16 + brow_l) * 272 +
                              (kk * 16 + bcol) * 2);
#pragma unroll
            for (int jj = 0; jj < 4; jj++)
                mma16816(aacc[jj], ar,
                         br[jj >> 1][(jj & 1) * 2], br[jj >> 1][(jj & 1) * 2 + 1]);
        }
        __half* sA = (__half*)(smraw + OA);
        int rg = lane >> 2, cg = lane & 3;
#pragma unroll
        for (int jj = 0; jj < 4; jj++) {
            int col = wn * 32 + jj * 8 + cg * 2;
            int r0 = wm * 16 + rg;
            sA[r0 * 72 + col]     = __float2half_rn((col     <= r0) ? aacc[jj][0] : 0.f);
            sA[r0 * 72 + col + 1] = __float2half_rn((col + 1 <= r0) ? aacc[jj][1] : 0.f);
            int r1 = r0 + 8;
            sA[r1 * 72 + col]     = __float2half_rn((col     <= r1) ? aacc[jj][2] : 0.f);
            sA[r1 * 72 + col + 1] = __float2half_rn((col + 1 <= r1) ? aacc[jj][3] : 0.f);
        }
    }
    __syncthreads();

    // phase 2: O = Q S + A V (64x128), warp tile 16x64
    float oacc[8][4];
#pragma unroll
    for (int j = 0; j < 8; j++)
#pragma unroll
        for (int r = 0; r < 4; r++) oacc[j][r] = 0.f;

    // QS: k over dk (8 steps), B from S[dk][dv] via trans ldmatrix
#pragma unroll
    for (int kk = 0; kk < 8; kk++) {
        uint32_t ar[4];
        ldsm4(ar, sb + OQ + (wm * 16 + arow_l) * 272 + (kk * 16 + acol) * 2);
        uint32_t bt[4][4];
#pragma unroll
        for (int jb = 0; jb < 4; jb++)
            ldsm4t(bt[jb], sb + OS + (kk * 16 + trow) * 272 +
                           (wn * 64 + jb * 16 + tcol) * 2);
#pragma unroll
        for (int j = 0; j < 8; j++)
            mma16816(oacc[j], ar,
                     bt[j >> 1][(j & 1) * 2], bt[j >> 1][(j & 1) * 2 + 1]);
    }
    // AV: k over s (4 steps), A from sA, B from V[s][dv] via trans ldmatrix
#pragma unroll
    for (int kk = 0; kk < 4; kk++) {
        uint32_t ar[4];
        ldsm4(ar, sb + OA + (wm * 16 + arow_l) * 144 + (kk * 16 + acol) * 2);
        uint32_t bt[4][4];
#pragma unroll
        for (int jb = 0; jb < 4; jb++)
            ldsm4t(bt[jb], sb + OV + (kk * 16 + trow) * 272 +
                           (wn * 64 + jb * 16 + tcol) * 2);
#pragma unroll
        for (int j = 0; j < 8; j++)
            mma16816(oacc[j], ar,
                     bt[j >> 1][(j & 1) * 2], bt[j >> 1][(j & 1) * 2 + 1]);
    }
    __syncthreads();   // all reads of Q/V/S done before aliasing with sO

    // store O to smem fp32
    {
        int rg = lane >> 2, cg = lane & 3;
#pragma unroll
        for (int j = 0; j < 8; j++) {
            int col = wn * 64 + j * 8 + cg * 2;
            int r0 = wm * 16 + rg;
            sO[r0 * 132 + col]       = oacc[j][0];
            sO[r0 * 132 + col + 1]   = oacc[j][1];
            sO[(r0 + 8) * 132 + col]     = oacc[j][2];
            sO[(r0 + 8) * 132 + col + 1] = oacc[j][3];
        }
    }
    __syncthreads();

    // fused RMSNorm + fp16 store (4 threads per row)
    {
        int r = tid >> 2, q = tid & 3;
        const float* row = sO + r * 132 + q * 32;
        float ss = 0.f;
#pragma unroll
        for (int i = 0; i < 32; i++) ss += row[i] * row[i];
        ss += __shfl_xor_sync(0xffffffffu, ss, 1);
        ss += __shfl_xor_sync(0xffffffffu, ss, 2);
        float rn = rsqrtf(ss * (1.f / 128.f) + 1e-6f);
        __half* orow = g_oA16 + ((size_t)(c * CH) + r) * 2048 + h * 128 + q * 32;
#pragma unroll
        for (int i = 0; i < 32; i++)
            orow[i] = __float2half_rn(row[i] * rn * __ldg(gnw + q * 32 + i));
    }
}

// ---------------- launch -------------------------------------------------------
extern "C" void kernel_launch(void* const* d_in, const int* in_sizes, int n_in,
                              void* d_out, int out_size) {
    const float* hidden = (const float*)d_in[0];
    const float* Wqkv   = (const float*)d_in[1];
    const float* bqkv   = (const float*)d_in[2];
    const float* gk_w0  = (const float*)d_in[3];
    const float* gk_w1  = (const float*)d_in[4];
    const float* gk_b1  = (const float*)d_in[5];
    const float* gnormw = (const float*)d_in[6];
    const float* Wo     = (const float*)d_in[7];
    float* out = (float*)d_out;

    float *p_qkv;
    __half *p_hA16, *p_Wqhi, *p_Wqlo, *p_Wohi, *p_Wolo, *p_oA16;
    cudaGetSymbolAddress((void**)&p_qkv, g_qkv);
    cudaGetSymbolAddress((void**)&p_hA16, g_hA16);
    cudaGetSymbolAddress((void**)&p_Wqhi, g_Wqhi);
    cudaGetSymbolAddress((void**)&p_Wqlo, g_Wqlo);
    cudaGetSymbolAddress((void**)&p_Wohi, g_Wohi);
    cudaGetSymbolAddress((void**)&p_Wolo, g_Wolo);
    cudaGetSymbolAddress((void**)&p_oA16, g_oA16);

    cudaFuncSetAttribute(gemm_mma, cudaFuncAttributeMaxDynamicSharedMemorySize, GSMEM);
    cudaFuncSetAttribute(out_kernel, cudaFuncAttributeMaxDynamicSharedMemorySize, OSMEM);

    // operand prep
    splitA16<<<(T_ * H_) / 1024, 256>>>(hidden, p_hA16);
    wsplit16<<<dim3(QKVW / 32, GK / 32), 256>>>(Wqkv, p_Wqhi, p_Wqlo, QKVW);
    wsplit16<<<dim3(H_ / 32, GK / 32), 256>>>(Wo, p_Wohi, p_Wolo, H_);

    // 1) qkv projection with fused bias/relu/scale
    gemm_mma<<<dim3(QKVW / 128, T_ / 128), 256, GSMEM>>>(
        p_hA16, p_Wqhi, p_Wqlo, bqkv, p_qkv, QKVW, 1);

    // 2) gate projections
    gk1_kernel<<<T_, 256>>>(hidden, gk_w0);
    gk2_kernel<<<(T_ * 512) / 256, 256>>>(gk_w1, gk_b1);

    // 3) chunked GLA
    chunkB_kernel<<<dim3(NC, NKV_), 128>>>();
    chunkP_kernel<<<dim3(NC, NKV_), 256>>>();
    combine_kernel<<<256, 256>>>();
    out_kernel<<<dim3(NC, NH_), 256, OSMEM>>>(gnormw);

    // 4) o_proj
    gemm_mma<<<dim3(H_ / 128, T_ / 128), 256, GSMEM>>>(
        p_oA16, p_Wohi, p_Wolo, nullptr, out, H_, 0);
}

// round 6
// speedup vs baseline: 5.0674x; 1.2232x over previous
#include <cuda_runtime.h>
#include <cuda_fp16.h>
#include <cstdint>
#include <math.h>

#define T_   8192
#define H_   2048
#define NH_  16
#define NKV_ 4
#define D_   128
#define CH   64
#define NC   128          // T_/CH
#define QKVW 3072
#define GK   2048

// ---------------- scratch (static device memory) ------------------------------
__device__ __align__(256) float g_qkv[(size_t)T_ * QKVW];
__device__ __align__(256) float g_tmp16[(size_t)T_ * 16];
__device__ __align__(256) float g_g[(size_t)T_ * 512];
__device__ __align__(256) float g_EB[(size_t)NC * NKV_ * D_];
__device__ __align__(256) float g_P[(size_t)NC * NKV_ * D_ * D_];
__device__ __align__(256) __half g_S16[(size_t)NC * NKV_ * D_ * D_];
// fp16 operands
__device__ __align__(256) __half g_hA16[(size_t)T_ * H_];
__device__ __align__(256) __half g_Wq16[(size_t)QKVW * GK];   // [N,K]
__device__ __align__(256) __half g_Wo16[(size_t)H_ * GK];     // [N,K]
__device__ __align__(256) __half g_oA16[(size_t)T_ * H_];
__device__ __align__(256) __half g_q16[(size_t)T_ * 2048];
__device__ __align__(256) __half g_k16[(size_t)T_ * 512];
__device__ __align__(256) __half g_v16[(size_t)T_ * 512];

// ======================= PTX helpers ==========================================
__device__ __forceinline__ uint32_t smem_u32(const void* p) {
    uint32_t a;
    asm("{ .reg .u64 t; cvta.to.shared.u64 t, %1; cvt.u32.u64 %0, t; }" : "=r"(a) : "l"(p));
    return a;
}
__device__ __forceinline__ void cpa16(uint32_t dst, const void* src) {
    asm volatile("cp.async.cg.shared.global [%0], [%1], 16;" :: "r"(dst), "l"(src));
}
__device__ __forceinline__ void ldsm4(uint32_t* r, uint32_t addr) {
    asm volatile("ldmatrix.sync.aligned.m8n8.x4.shared.b16 {%0,%1,%2,%3}, [%4];"
                 : "=r"(r[0]), "=r"(r[1]), "=r"(r[2]), "=r"(r[3]) : "r"(addr));
}
__device__ __forceinline__ void ldsm4t(uint32_t* r, uint32_t addr) {
    asm volatile("ldmatrix.sync.aligned.m8n8.x4.trans.shared.b16 {%0,%1,%2,%3}, [%4];"
                 : "=r"(r[0]), "=r"(r[1]), "=r"(r[2]), "=r"(r[3]) : "r"(addr));
}
__device__ __forceinline__ void mma16816(float* d, const uint32_t* a,
                                         uint32_t b0, uint32_t b1) {
    asm volatile("mma.sync.aligned.m16n8k16.row.col.f32.f16.f16.f32 "
                 "{%0,%1,%2,%3}, {%4,%5,%6,%7}, {%8,%9}, {%0,%1,%2,%3};"
                 : "+f"(d[0]), "+f"(d[1]), "+f"(d[2]), "+f"(d[3])
                 : "r"(a[0]), "r"(a[1]), "r"(a[2]), "r"(a[3]), "r"(b0), "r"(b1));
}

// ======================= conversions ==========================================
__global__ void __launch_bounds__(256) splitA16(const float* __restrict__ src,
                                                __half* __restrict__ dst) {
    size_t i4 = ((size_t)blockIdx.x * 256 + threadIdx.x) * 4;
    float4 v = *(const float4*)(src + i4);
    __half2* d = (__half2*)(dst + i4);
    d[0] = __floats2half2_rn(v.x, v.y);
    d[1] = __floats2half2_rn(v.z, v.w);
}

// W [K=2048, N] fp32 -> [N, K=2048] fp16
__global__ void __launch_bounds__(256) wtrans16(const float* __restrict__ W,
                                                __half* __restrict__ out, int N) {
    __shared__ float t[32][33];
    int bx = blockIdx.x, by = blockIdx.y;
    int lx = threadIdx.x & 31, ly = threadIdx.x >> 5;
    for (int r = ly; r < 32; r += 8)
        t[r][lx] = W[(size_t)(by * 32 + r) * N + bx * 32 + lx];
    __syncthreads();
    for (int r = ly; r < 32; r += 8)
        out[(size_t)(bx * 32 + r) * GK + by * 32 + lx] = __float2half_rn(t[lx][r]);
}

// ======================= HMMA GEMM: single fp16 plane ==========================
// C[M,N] = A16 @ B16^T. CTA 128x256, 8 warps (warp tile 64x64), K-chunk 32,
// 4-stage cp.async, single __syncthreads per chunk.
#define ROWB   80
#define ATILE  (128 * ROWB)          // 10240
#define BTILE  (256 * ROWB)          // 20480
#define STAGEB (ATILE + BTILE)       // 30720
#define GSMEM  (4 * STAGEB)          // 122880

__global__ void __launch_bounds__(256) gemm_mma(
    const __half* __restrict__ A16, const __half* __restrict__ B16,
    const float* __restrict__ bias, float* __restrict__ C, int N, int mode) {
    extern __shared__ char smraw[];
    uint32_t sbase = smem_u32(smraw);
    int tid = threadIdx.x, wid = tid >> 5, lane = tid & 31;
    int tm = blockIdx.y * 128, tn = blockIdx.x * 256;
    int wm = wid & 1, wn = wid >> 1;

    float acc[4][8][4];
#pragma unroll
    for (int i = 0; i < 4; i++)
#pragma unroll
        for (int j = 0; j < 8; j++)
#pragma unroll
            for (int r = 0; r < 4; r++) acc[i][j][r] = 0.f;

    auto issue_load = [&](int k0i, int stage) {
        int k0 = k0i * 32;
        uint32_t sb = sbase + stage * STAGEB;
#pragma unroll
        for (int it = 0; it < 6; it++) {
            int u = tid + it * 256;
            const __half* src;
            uint32_t dst;
            if (u < 512) {
                int row = u >> 2, chunk = u & 3;
                src = A16 + (size_t)(tm + row) * GK + k0 + chunk * 8;
                dst = sb + row * ROWB + chunk * 16;
            } else {
                int v = u - 512;
                int row = v >> 2, chunk = v & 3;
                src = B16 + (size_t)(tn + row) * GK + k0 + chunk * 8;
                dst = sb + ATILE + row * ROWB + chunk * 16;
            }
            cpa16(dst, src);
        }
        asm volatile("cp.async.commit_group;" ::: "memory");
    };

    issue_load(0, 0);
    issue_load(1, 1);
    issue_load(2, 2);

    int arow_l = (lane & 7) + ((lane >> 3) & 1) * 8;
    int acol   = (lane >> 4) * 8;
    int brow_l = (lane & 7) + ((lane >> 4) & 1) * 8;
    int bcol   = ((lane >> 3) & 1) * 8;

    for (int kc = 0; kc < 64; kc++) {
        if (kc < 62)       asm volatile("cp.async.wait_group 2;" ::: "memory");
        else if (kc == 62) asm volatile("cp.async.wait_group 1;" ::: "memory");
        else               asm volatile("cp.async.wait_group 0;" ::: "memory");
        __syncthreads();
        if (kc + 3 < 64) issue_load(kc + 3, (kc + 3) & 3);

        uint32_t sb = sbase + (kc & 3) * STAGEB;
#pragma unroll
        for (int ks = 0; ks < 2; ks++) {
            uint32_t a_regs[4][4];
#pragma unroll
            for (int i = 0; i < 4; i++)
                ldsm4(a_regs[i],
                      sb + (wm * 64 + i * 16 + arow_l) * ROWB + (ks * 16 + acol) * 2);
            uint32_t b_regs[4][4];
#pragma unroll
            for (int j = 0; j < 4; j++)
                ldsm4(b_regs[j], sb + ATILE +
                      (wn * 64 + j * 16 + brow_l) * ROWB + (ks * 16 + bcol) * 2);
#pragma unroll
            for (int i = 0; i < 4; i++)
#pragma unroll
                for (int j = 0; j < 8; j++)
                    mma16816(acc[i][j], a_regs[i],
                             b_regs[j >> 1][(j & 1) * 2], b_regs[j >> 1][(j & 1) * 2 + 1]);
        }
    }

    int g = lane >> 2, tg = lane & 3;
#pragma unroll
    for (int i = 0; i < 4; i++) {
        int row0 = tm + wm * 64 + i * 16 + g;
#pragma unroll
        for (int j = 0; j < 8; j++) {
            int col = tn + wn * 64 + j * 8 + tg * 2;
            float v0 = acc[i][j][0], v1 = acc[i][j][1];
            float v2 = acc[i][j][2], v3 = acc[i][j][3];
            if (bias) {
                float b0 = bias[col], b1 = bias[col + 1];
                v0 += b0; v1 += b1; v2 += b0; v3 += b1;
            }
            if (mode) {
                if (col < 2560) {
                    v0 = fmaxf(v0, 0.f); v1 = fmaxf(v1, 0.f);
                    v2 = fmaxf(v2, 0.f); v3 = fmaxf(v3, 0.f);
                    if (col < 2048) {
                        const float s = 0.08838834764831843f;
                        v0 *= s; v1 *= s; v2 *= s; v3 *= s;
                    }
                }
            }
            *(float2*)(C + (size_t)row0 * N + col)       = make_float2(v0, v1);
            *(float2*)(C + (size_t)(row0 + 8) * N + col) = make_float2(v2, v3);
        }
    }
}

// ---------------- gate low-rank projections -----------------------------------
__global__ void __launch_bounds__(256) gk1_kernel(const float* __restrict__ hidden,
                                                  const float* __restrict__ w0) {
    int t = blockIdx.x, tid = threadIdx.x;
    float acc[16];
#pragma unroll
    for (int r = 0; r < 16; r++) acc[r] = 0.f;
    const float* hrow = hidden + (size_t)t * H_;
    for (int h = tid; h < H_; h += 256) {
        float x = hrow[h];
        const float4* w = (const float4*)(w0 + (size_t)h * 16);
#pragma unroll
        for (int q = 0; q < 4; q++) {
            float4 w4 = w[q];
            acc[q * 4 + 0] += x * w4.x;
            acc[q * 4 + 1] += x * w4.y;
            acc[q * 4 + 2] += x * w4.z;
            acc[q * 4 + 3] += x * w4.w;
        }
    }
    __shared__ float sred[256][16];
#pragma unroll
    for (int r = 0; r < 16; r++) sred[tid][r] = acc[r];
    __syncthreads();
    if (tid < 16) {
        float s = 0.f;
        for (int i = 0; i < 256; i++) s += sred[i][tid];
        g_tmp16[(size_t)t * 16 + tid] = s;
    }
}

__global__ void __launch_bounds__(256) gk2_kernel(const float* __restrict__ w1,
                                                  const float* __restrict__ b1) {
    int idx = blockIdx.x * 256 + threadIdx.x;
    int t = idx >> 9, n = idx & 511;
    const float* tp = g_tmp16 + (size_t)t * 16;
    float x = b1[n];
#pragma unroll
    for (int r = 0; r < 16; r++) x += tp[r] * w1[r * 512 + n];
    float ls = (x >= 0.f) ? (-log1pf(expf(-x))) : (x - log1pf(expf(x)));
    g_g[(size_t)t * 512 + n] = ls * (1.f / 16.f);
}

// ---------------- per-chunk cumsum + fp16 operand emit -------------------------
__global__ void __launch_bounds__(128) chunkB_kernel() {
    int c = blockIdx.x, kv = blockIdx.y, d = threadIdx.x;
    float cum = 0.f;
    for (int t = 0; t < CH; t++) {
        size_t tg = (size_t)c * CH + t;
        cum += g_g[tg * 512 + kv * 128 + d];
        float eB = expf(cum), eBn = expf(-cum);
        size_t rb = tg * QKVW;
        g_k16[tg * 512 + kv * 128 + d] =
            __float2half_rn(g_qkv[rb + 2048 + kv * 128 + d] * eBn);
        g_v16[tg * 512 + kv * 128 + d] =
            __float2half_rn(g_qkv[rb + 2560 + kv * 128 + d]);
#pragma unroll
        for (int r = 0; r < 4; r++)
            g_q16[tg * 2048 + (kv * 4 + r) * 128 + d] =
                __float2half_rn(g_qkv[rb + (kv * 4 + r) * 128 + d] * eB);
    }
    g_EB[(size_t)(c * 4 + kv) * 128 + d] = expf(cum);
}

// ---------------- per-chunk increment P = exp(Btot) ⊙ (K~^T V) ----------------
__global__ void __launch_bounds__(256) chunkP_kernel() {
    __shared__ float sv[CH * 128];
    int c = blockIdx.x, kv = blockIdx.y, tid = threadIdx.x;
    for (int i = tid; i < CH * 64; i += 256) {
        int r = i >> 6, c2 = i & 63;
        __half2 hv = *(const __half2*)(g_v16 + ((size_t)(c * CH + r)) * 512 +
                                       kv * 128 + c2 * 2);
        float2 f = __half22float2(hv);
        sv[r * 128 + c2 * 2] = f.x;
        sv[r * 128 + c2 * 2 + 1] = f.y;
    }
    __syncthreads();
    int dk = tid >> 1, half = (tid & 1) * 64;
    float4 acc[16];
#pragma unroll
    for (int j = 0; j < 16; j++) acc[j] = make_float4(0.f, 0.f, 0.f, 0.f);
    for (int t = 0; t < CH; t++) {
        float kk = __half2float(g_k16[((size_t)(c * CH + t)) * 512 + kv * 128 + dk]);
        const float4* vr = (const float4*)(sv + t * 128 + half);
#pragma unroll
        for (int j = 0; j < 16; j++) {
            float4 v = vr[j];
            acc[j].x += kk * v.x; acc[j].y += kk * v.y;
            acc[j].z += kk * v.z; acc[j].w += kk * v.w;
        }
    }
    float eb = g_EB[(size_t)(c * 4 + kv) * 128 + dk];
    float4* pp = (float4*)(g_P + (((size_t)(c * 4 + kv)) * 128 + dk) * 128 + half);
#pragma unroll
    for (int j = 0; j < 16; j++) {
        float4 v = acc[j];
        v.x *= eb; v.y *= eb; v.z *= eb; v.w *= eb;
        pp[j] = v;
    }
}

// ---------------- inter-chunk combine: element-parallel, fp16 S out ------------
__global__ void __launch_bounds__(256) combine_kernel() {
    int g = blockIdx.x * 256 + threadIdx.x;
    int dv = g & 127, dk = (g >> 7) & 127, kv = g >> 14;
    float s = 0.f;
    for (int c = 0; c < NC; c++) {
        size_t idx = ((size_t)(c * 4 + kv) * 128 + dk) * 128 + dv;
        g_S16[idx] = __float2half_rn(s);
        float eb = g_EB[(size_t)(c * 4 + kv) * 128 + dk];
        s = eb * s + g_P[idx];
    }
}

// ---------------- intra-chunk output via mma + fused RMSNorm -------------------
#define OQ  0
#define OK  17408
#define OV  34816
#define OS  52224
#define OA  87040
#define OSMEM 96256

__global__ void __launch_bounds__(256) out_kernel(const float* __restrict__ gnw) {
    extern __shared__ char smraw[];
    uint32_t sb = smem_u32(smraw);
    float* sO = (float*)smraw;
    int c = blockIdx.x, h = blockIdx.y, kv = h >> 2;
    int tid = threadIdx.x, wid = tid >> 5, lane = tid & 31;
    int wm = wid >> 1, wn = wid & 1;

    {
        const __half* qg = g_q16 + (size_t)c * CH * 2048 + h * 128;
        const __half* kg = g_k16 + (size_t)c * CH * 512 + kv * 128;
        const __half* vg = g_v16 + (size_t)c * CH * 512 + kv * 128;
        const __half* sg = g_S16 + (size_t)(c * 4 + kv) * 16384;
        for (int u = tid; u < 5120; u += 256) {
            int r, ch;
            if (u < 1024) {
                r = u >> 4; ch = u & 15;
                cpa16(sb + OQ + r * 272 + ch * 16, qg + (size_t)r * 2048 + ch * 8);
            } else if (u < 2048) {
                int v = u - 1024; r = v >> 4; ch = v & 15;
                cpa16(sb + OK + r * 272 + ch * 16, kg + (size_t)r * 512 + ch * 8);
            } else if (u < 3072) {
                int v = u - 2048; r = v >> 4; ch = v & 15;
                cpa16(sb + OV + r * 272 + ch * 16, vg + (size_t)r * 512 + ch * 8);
            } else {
                int v = u - 3072; r = v >> 4; ch = v & 15;
                cpa16(sb + OS + r * 272 + ch * 16, sg + (size_t)r * 128 + ch * 8);
            }
        }
        asm volatile("cp.async.commit_group;" ::: "memory");
        asm volatile("cp.async.wait_group 0;" ::: "memory");
        __syncthreads();
    }

    int arow_l = (lane & 7) + ((lane >> 3) & 1) * 8;
    int acol   = (lane >> 4) * 8;
    int brow_l = (lane & 7) + ((lane >> 4) & 1) * 8;
    int bcol   = ((lane >> 3) & 1) * 8;
    int trow   = lane & 15;
    int tcol   = (lane >> 4) * 8;

    // phase 1: A = Q K^T (64x64), causal mask -> sA fp16
    {
        float aacc[4][4];
#pragma unroll
        for (int i = 0; i < 4; i++)
#pragma unroll
            for (int j = 0; j < 4; j++) aacc[i][j] = 0.f;
#pragma unroll
        for (int kk = 0; kk < 8; kk++) {
            uint32_t ar[4];
            ldsm4(ar, sb + OQ + (wm * 16 + arow_l) * 272 + (kk * 16 + acol) * 2);
            uint32_t br[2][4];
#pragma unroll
            for (int j = 0; j < 2; j++)
                ldsm4(br[j], sb + OK + (wn * 32 + j * 16 + brow_l) * 272 +
                              (kk * 16 + bcol) * 2);
#pragma unroll
            for (int jj = 0; jj < 4; jj++)
                mma16816(aacc[jj], ar,
                         br[jj >> 1][(jj & 1) * 2], br[jj >> 1][(jj & 1) * 2 + 1]);
        }
        __half* sA = (__half*)(smraw + OA);
        int rg = lane >> 2, cg = lane & 3;
#pragma unroll
        for (int jj = 0; jj < 4; jj++) {
            int col = wn * 32 + jj * 8 + cg * 2;
            int r0 = wm * 16 + rg;
            sA[r0 * 72 + col]     = __float2half_rn((col     <= r0) ? aacc[jj][0] : 0.f);
            sA[r0 * 72 + col + 1] = __float2half_rn((col + 1 <= r0) ? aacc[jj][1] : 0.f);
            int r1 = r0 + 8;
            sA[r1 * 72 + col]     = __float2half_rn((col     <= r1) ? aacc[jj][2] : 0.f);
            sA[r1 * 72 + col + 1] = __float2half_rn((col + 1 <= r1) ? aacc[jj][3] : 0.f);
        }
    }
    __syncthreads();

    // phase 2: O = Q S + A V (64x128), warp tile 16x64
    float oacc[8][4];
#pragma unroll
    for (int j = 0; j < 8; j++)
#pragma unroll
        for (int r = 0; r < 4; r++) oacc[j][r] = 0.f;

#pragma unroll
    for (int kk = 0; kk < 8; kk++) {
        uint32_t ar[4];
        ldsm4(ar, sb + OQ + (wm * 16 + arow_l) * 272 + (kk * 16 + acol) * 2);
        uint32_t bt[4][4];
#pragma unroll
        for (int jb = 0; jb < 4; jb++)
            ldsm4t(bt[jb], sb + OS + (kk * 16 + trow) * 272 +
                           (wn * 64 + jb * 16 + tcol) * 2);
#pragma unroll
        for (int j = 0; j < 8; j++)
            mma16816(oacc[j], ar,
                     bt[j >> 1][(j & 1) * 2], bt[j >> 1][(j & 1) * 2 + 1]);
    }
#pragma unroll
    for (int kk = 0; kk < 4; kk++) {
        uint32_t ar[4];
        ldsm4(ar, sb + OA + (wm * 16 + arow_l) * 144 + (kk * 16 + acol) * 2);
        uint32_t bt[4][4];
#pragma unroll
        for (int jb = 0; jb < 4; jb++)
            ldsm4t(bt[jb], sb + OV + (kk * 16 + trow) * 272 +
                           (wn * 64 + jb * 16 + tcol) * 2);
#pragma unroll
        for (int j = 0; j < 8; j++)
            mma16816(oacc[j], ar,
                     bt[j >> 1][(j & 1) * 2], bt[j >> 1][(j & 1) * 2 + 1]);
    }
    __syncthreads();

    {
        int rg = lane >> 2, cg = lane & 3;
#pragma unroll
        for (int j = 0; j < 8; j++) {
            int col = wn * 64 + j * 8 + cg * 2;
            int r0 = wm * 16 + rg;
            sO[r0 * 132 + col]       = oacc[j][0];
            sO[r0 * 132 + col + 1]   = oacc[j][1];
            sO[(r0 + 8) * 132 + col]     = oacc[j][2];
            sO[(r0 + 8) * 132 + col + 1] = oacc[j][3];
        }
    }
    __syncthreads();

    {
        int r = tid >> 2, q = tid & 3;
        const float* row = sO + r * 132 + q * 32;
        float ss = 0.f;
#pragma unroll
        for (int i = 0; i < 32; i++) ss += row[i] * row[i];
        ss += __shfl_xor_sync(0xffffffffu, ss, 1);
        ss += __shfl_xor_sync(0xffffffffu, ss, 2);
        float rn = rsqrtf(ss * (1.f / 128.f) + 1e-6f);
        __half* orow = g_oA16 + ((size_t)(c * CH) + r) * 2048 + h * 128 + q * 32;
#pragma unroll
        for (int i = 0; i < 32; i++)
            orow[i] = __float2half_rn(row[i] * rn * __ldg(gnw + q * 32 + i));
    }
}

// ---------------- launch -------------------------------------------------------
extern "C" void kernel_launch(void* const* d_in, const int* in_sizes, int n_in,
                              void* d_out, int out_size) {
    const float* hidden = (const float*)d_in[0];
    const float* Wqkv   = (const float*)d_in[1];
    const float* bqkv   = (const float*)d_in[2];
    const float* gk_w0  = (const float*)d_in[3];
    const float* gk_w1  = (const float*)d_in[4];
    const float* gk_b1  = (const float*)d_in[5];
    const float* gnormw = (const float*)d_in[6];
    const float* Wo     = (const float*)d_in[7];
    float* out = (float*)d_out;

    float *p_qkv;
    __half *p_hA16, *p_Wq16, *p_Wo16, *p_oA16;
    cudaGetSymbolAddress((void**)&p_qkv, g_qkv);
    cudaGetSymbolAddress((void**)&p_hA16, g_hA16);
    cudaGetSymbolAddress((void**)&p_Wq16, g_Wq16);
    cudaGetSymbolAddress((void**)&p_Wo16, g_Wo16);
    cudaGetSymbolAddress((void**)&p_oA16, g_oA16);

    cudaFuncSetAttribute(gemm_mma, cudaFuncAttributeMaxDynamicSharedMemorySize, GSMEM);
    cudaFuncSetAttribute(out_kernel, cudaFuncAttributeMaxDynamicSharedMemorySize, OSMEM);

    // operand prep
    splitA16<<<(T_ * H_) / 1024, 256>>>(hidden, p_hA16);
    wtrans16<<<dim3(QKVW / 32, GK / 32), 256>>>(Wqkv, p_Wq16, QKVW);
    wtrans16<<<dim3(H_ / 32, GK / 32), 256>>>(Wo, p_Wo16, H_);

    // 1) qkv projection with fused bias/relu/scale
    gemm_mma<<<dim3(QKVW / 256, T_ / 128), 256, GSMEM>>>(
        p_hA16, p_Wq16, bqkv, p_qkv, QKVW, 1);

    // 2) gate projections
    gk1_kernel<<<T_, 256>>>(hidden, gk_w0);
    gk2_kernel<<<(T_ * 512) / 256, 256>>>(gk_w1, gk_b1);

    // 3) chunked GLA
    chunkB_kernel<<<dim3(NC, NKV_), 128>>>();
    chunkP_kernel<<<dim3(NC, NKV_), 256>>>();
    combine_kernel<<<256, 256>>>();
    out_kernel<<<dim3(NC, NH_), 256, OSMEM>>>(gnormw);

    // 4) o_proj
    gemm_mma<<<dim3(H_ / 256, T_ / 128), 256, GSMEM>>>(
        p_oA16, p_Wo16, nullptr, out, H_, 0);
}

// round 7
// speedup vs baseline: 5.6283x; 1.1107x over previous
#include <cuda_runtime.h>
#include <cuda_fp16.h>
#include <cstdint>
#include <math.h>

#define T_   8192
#define H_   2048
#define NH_  16
#define NKV_ 4
#define D_   128
#define CH   64
#define NC   128          // T_/CH
#define QKVW 3072
#define GK   2048

// ---------------- scratch (static device memory) ------------------------------
__device__ __align__(256) float g_tmp16[(size_t)T_ * 16];
__device__ __align__(256) float g_g[(size_t)T_ * 512];
__device__ __align__(256) float g_EB[(size_t)NC * NKV_ * D_];
__device__ __align__(256) float g_P[(size_t)NC * NKV_ * D_ * D_];
__device__ __align__(256) __half g_S16[(size_t)NC * NKV_ * D_ * D_];
// fp16 operands
__device__ __align__(256) __half g_hA16[(size_t)T_ * H_];
__device__ __align__(256) __half g_Wq16[(size_t)QKVW * GK];   // [N,K]
__device__ __align__(256) __half g_Wo16[(size_t)H_ * GK];     // [N,K]
__device__ __align__(256) __half g_oA16[(size_t)T_ * H_];
__device__ __align__(256) __half g_q16[(size_t)T_ * 2048];
__device__ __align__(256) __half g_k16[(size_t)T_ * 512];
__device__ __align__(256) __half g_v16[(size_t)T_ * 512];

// ======================= PTX helpers ==========================================
__device__ __forceinline__ uint32_t smem_u32(const void* p) {
    uint32_t a;
    asm("{ .reg .u64 t; cvta.to.shared.u64 t, %1; cvt.u32.u64 %0, t; }" : "=r"(a) : "l"(p));
    return a;
}
__device__ __forceinline__ void cpa16(uint32_t dst, const void* src) {
    asm volatile("cp.async.cg.shared.global [%0], [%1], 16;" :: "r"(dst), "l"(src));
}
__device__ __forceinline__ void ldsm4(uint32_t* r, uint32_t addr) {
    asm volatile("ldmatrix.sync.aligned.m8n8.x4.shared.b16 {%0,%1,%2,%3}, [%4];"
                 : "=r"(r[0]), "=r"(r[1]), "=r"(r[2]), "=r"(r[3]) : "r"(addr));
}
__device__ __forceinline__ void ldsm4t(uint32_t* r, uint32_t addr) {
    asm volatile("ldmatrix.sync.aligned.m8n8.x4.trans.shared.b16 {%0,%1,%2,%3}, [%4];"
                 : "=r"(r[0]), "=r"(r[1]), "=r"(r[2]), "=r"(r[3]) : "r"(addr));
}
__device__ __forceinline__ void mma16816(float* d, const uint32_t* a,
                                         uint32_t b0, uint32_t b1) {
    asm volatile("mma.sync.aligned.m16n8k16.row.col.f32.f16.f16.f32 "
                 "{%0,%1,%2,%3}, {%4,%5,%6,%7}, {%8,%9}, {%0,%1,%2,%3};"
                 : "+f"(d[0]), "+f"(d[1]), "+f"(d[2]), "+f"(d[3])
                 : "r"(a[0]), "r"(a[1]), "r"(a[2]), "r"(a[3]), "r"(b0), "r"(b1));
}

// ======================= conversions ==========================================
__global__ void __launch_bounds__(256) splitA16(const float* __restrict__ src,
                                                __half* __restrict__ dst) {
    size_t i4 = ((size_t)blockIdx.x * 256 + threadIdx.x) * 4;
    float4 v = *(const float4*)(src + i4);
    __half2* d = (__half2*)(dst + i4);
    d[0] = __floats2half2_rn(v.x, v.y);
    d[1] = __floats2half2_rn(v.z, v.w);
}

__global__ void __launch_bounds__(256) wtrans16(const float* __restrict__ W,
                                                __half* __restrict__ out, int N) {
    __shared__ float t[32][33];
    int bx = blockIdx.x, by = blockIdx.y;
    int lx = threadIdx.x & 31, ly = threadIdx.x >> 5;
    for (int r = ly; r < 32; r += 8)
        t[r][lx] = W[(size_t)(by * 32 + r) * N + bx * 32 + lx];
    __syncthreads();
    for (int r = ly; r < 32; r += 8)
        out[(size_t)(bx * 32 + r) * GK + by * 32 + lx] = __float2half_rn(t[lx][r]);
}

// ======================= HMMA GEMM: 512 threads, 128x256 tile ==================
// mode 1: qkv projection; epilogue writes fp16 q/k/v buffers directly.
// mode 0: writes fp32 C.
#define ROWB   80
#define ATILE  (128 * ROWB)
#define BTILE  (256 * ROWB)
#define STAGEB (ATILE + BTILE)       // 30720
#define GSMEM  (4 * STAGEB)          // 122880

__global__ void __launch_bounds__(512) gemm_mma(
    const __half* __restrict__ A16, const __half* __restrict__ B16,
    const float* __restrict__ bias, float* __restrict__ C, int N, int mode) {
    extern __shared__ char smraw[];
    uint32_t sbase = smem_u32(smraw);
    int tid = threadIdx.x, wid = tid >> 5, lane = tid & 31;
    int tm = blockIdx.y * 128, tn = blockIdx.x * 256;
    int wm = wid & 3, wn = wid >> 2;      // warp tile 32(M) x 64(N)

    float acc[2][8][4];
#pragma unroll
    for (int i = 0; i < 2; i++)
#pragma unroll
        for (int j = 0; j < 8; j++)
#pragma unroll
            for (int r = 0; r < 4; r++) acc[i][j][r] = 0.f;

    auto issue_load = [&](int k0i, int stage) {
        int k0 = k0i * 32;
        uint32_t sb = sbase + stage * STAGEB;
#pragma unroll
        for (int it = 0; it < 3; it++) {
            int u = tid + it * 512;
            const __half* src;
            uint32_t dst;
            if (u < 512) {
                int row = u >> 2, chunk = u & 3;
                src = A16 + (size_t)(tm + row) * GK + k0 + chunk * 8;
                dst = sb + row * ROWB + chunk * 16;
            } else {
                int v = u - 512;
                int row = v >> 2, chunk = v & 3;
                src = B16 + (size_t)(tn + row) * GK + k0 + chunk * 8;
                dst = sb + ATILE + row * ROWB + chunk * 16;
            }
            cpa16(dst, src);
        }
        asm volatile("cp.async.commit_group;" ::: "memory");
    };

    issue_load(0, 0);
    issue_load(1, 1);
    issue_load(2, 2);

    int arow_l = (lane & 7) + ((lane >> 3) & 1) * 8;
    int acol   = (lane >> 4) * 8;
    int brow_l = (lane & 7) + ((lane >> 4) & 1) * 8;
    int bcol   = ((lane >> 3) & 1) * 8;

    for (int kc = 0; kc < 64; kc++) {
        if (kc < 62)       asm volatile("cp.async.wait_group 2;" ::: "memory");
        else if (kc == 62) asm volatile("cp.async.wait_group 1;" ::: "memory");
        else               asm volatile("cp.async.wait_group 0;" ::: "memory");
        __syncthreads();
        if (kc + 3 < 64) issue_load(kc + 3, (kc + 3) & 3);

        uint32_t sb = sbase + (kc & 3) * STAGEB;
#pragma unroll
        for (int ks = 0; ks < 2; ks++) {
            uint32_t a_regs[2][4];
#pragma unroll
            for (int i = 0; i < 2; i++)
                ldsm4(a_regs[i],
                      sb + (wm * 32 + i * 16 + arow_l) * ROWB + (ks * 16 + acol) * 2);
            uint32_t b_regs[4][4];
#pragma unroll
            for (int j = 0; j < 4; j++)
                ldsm4(b_regs[j], sb + ATILE +
                      (wn * 64 + j * 16 + brow_l) * ROWB + (ks * 16 + bcol) * 2);
#pragma unroll
            for (int i = 0; i < 2; i++)
#pragma unroll
                for (int j = 0; j < 8; j++)
                    mma16816(acc[i][j], a_regs[i],
                             b_regs[j >> 1][(j & 1) * 2], b_regs[j >> 1][(j & 1) * 2 + 1]);
        }
    }

    int g = lane >> 2, tg = lane & 3;
#pragma unroll
    for (int i = 0; i < 2; i++) {
        int row0 = tm + wm * 32 + i * 16 + g;
#pragma unroll
        for (int j = 0; j < 8; j++) {
            int col = tn + wn * 64 + j * 8 + tg * 2;
            float v0 = acc[i][j][0], v1 = acc[i][j][1];
            float v2 = acc[i][j][2], v3 = acc[i][j][3];
            if (mode) {
                float b0 = bias[col], b1 = bias[col + 1];
                v0 += b0; v1 += b1; v2 += b0; v3 += b1;
                if (col < 2560) {
                    v0 = fmaxf(v0, 0.f); v1 = fmaxf(v1, 0.f);
                    v2 = fmaxf(v2, 0.f); v3 = fmaxf(v3, 0.f);
                    if (col < 2048) {
                        const float s = 0.08838834764831843f;
                        v0 *= s; v1 *= s; v2 *= s; v3 *= s;
                    }
                }
                __half2 h0 = __floats2half2_rn(v0, v1);
                __half2 h1 = __floats2half2_rn(v2, v3);
                if (col < 2048) {
                    *(__half2*)(g_q16 + (size_t)row0 * 2048 + col) = h0;
                    *(__half2*)(g_q16 + (size_t)(row0 + 8) * 2048 + col) = h1;
                } else if (col < 2560) {
                    *(__half2*)(g_k16 + (size_t)row0 * 512 + col - 2048) = h0;
                    *(__half2*)(g_k16 + (size_t)(row0 + 8) * 512 + col - 2048) = h1;
                } else {
                    *(__half2*)(g_v16 + (size_t)row0 * 512 + col - 2560) = h0;
                    *(__half2*)(g_v16 + (size_t)(row0 + 8) * 512 + col - 2560) = h1;
                }
            } else {
                *(float2*)(C + (size_t)row0 * N + col)       = make_float2(v0, v1);
                *(float2*)(C + (size_t)(row0 + 8) * N + col) = make_float2(v2, v3);
            }
        }
    }
}

// ---------------- gate low-rank projections -----------------------------------
__global__ void __launch_bounds__(256) gk1_kernel(const float* __restrict__ hidden,
                                                  const float* __restrict__ w0) {
    int t = blockIdx.x, tid = threadIdx.x;
    float acc[16];
#pragma unroll
    for (int r = 0; r < 16; r++) acc[r] = 0.f;
    const float* hrow = hidden + (size_t)t * H_;
    for (int h = tid; h < H_; h += 256) {
        float x = hrow[h];
        const float4* w = (const float4*)(w0 + (size_t)h * 16);
#pragma unroll
        for (int q = 0; q < 4; q++) {
            float4 w4 = w[q];
            acc[q * 4 + 0] += x * w4.x;
            acc[q * 4 + 1] += x * w4.y;
            acc[q * 4 + 2] += x * w4.z;
            acc[q * 4 + 3] += x * w4.w;
        }
    }
    __shared__ float sred[256][16];
#pragma unroll
    for (int r = 0; r < 16; r++) sred[tid][r] = acc[r];
    __syncthreads();
    if (tid < 16) {
        float s = 0.f;
        for (int i = 0; i < 256; i++) s += sred[i][tid];
        g_tmp16[(size_t)t * 16 + tid] = s;
    }
}

__global__ void __launch_bounds__(256) gk2_kernel(const float* __restrict__ w1,
                                                  const float* __restrict__ b1) {
    int idx = blockIdx.x * 256 + threadIdx.x;
    int t = idx >> 9, n = idx & 511;
    const float* tp = g_tmp16 + (size_t)t * 16;
    float x = b1[n];
#pragma unroll
    for (int r = 0; r < 16; r++) x += tp[r] * w1[r * 512 + n];
    float ls = (x >= 0.f) ? (-log1pf(expf(-x))) : (x - log1pf(expf(x)));
    g_g[(size_t)t * 512 + n] = ls * (1.f / 16.f);
}

// ---------------- per-chunk cumsum + fp16 q/k scaling in place ----------------
__global__ void __launch_bounds__(128) chunkB_kernel() {
    int c = blockIdx.x, kv = blockIdx.y, d = threadIdx.x;
    float cum = 0.f;
    for (int t = 0; t < CH; t++) {
        size_t tg = (size_t)c * CH + t;
        cum += g_g[tg * 512 + kv * 128 + d];
        float eB = expf(cum), eBn = expf(-cum);
        size_t ok = tg * 512 + kv * 128 + d;
        g_k16[ok] = __float2half_rn(__half2float(g_k16[ok]) * eBn);
#pragma unroll
        for (int r = 0; r < 4; r++) {
            size_t oq = tg * 2048 + (kv * 4 + r) * 128 + d;
            g_q16[oq] = __float2half_rn(__half2float(g_q16[oq]) * eB);
        }
    }
    g_EB[(size_t)(c * 4 + kv) * 128 + d] = expf(cum);
}

// ---------------- per-chunk increment P = exp(Btot) ⊙ (K~^T V) ----------------
__global__ void __launch_bounds__(256) chunkP_kernel() {
    __shared__ float sv[CH * 128];
    int c = blockIdx.x, kv = blockIdx.y, tid = threadIdx.x;
    for (int i = tid; i < CH * 64; i += 256) {
        int r = i >> 6, c2 = i & 63;
        __half2 hv = *(const __half2*)(g_v16 + ((size_t)(c * CH + r)) * 512 +
                                       kv * 128 + c2 * 2);
        float2 f = __half22float2(hv);
        sv[r * 128 + c2 * 2] = f.x;
        sv[r * 128 + c2 * 2 + 1] = f.y;
    }
    __syncthreads();
    int dk = tid >> 1, half = (tid & 1) * 64;
    float4 acc[16];
#pragma unroll
    for (int j = 0; j < 16; j++) acc[j] = make_float4(0.f, 0.f, 0.f, 0.f);
    for (int t = 0; t < CH; t++) {
        float kk = __half2float(g_k16[((size_t)(c * CH + t)) * 512 + kv * 128 + dk]);
        const float4* vr = (const float4*)(sv + t * 128 + half);
#pragma unroll
        for (int j = 0; j < 16; j++) {
            float4 v = vr[j];
            acc[j].x += kk * v.x; acc[j].y += kk * v.y;
            acc[j].z += kk * v.z; acc[j].w += kk * v.w;
        }
    }
    float eb = g_EB[(size_t)(c * 4 + kv) * 128 + dk];
    float4* pp = (float4*)(g_P + (((size_t)(c * 4 + kv)) * 128 + dk) * 128 + half);
#pragma unroll
    for (int j = 0; j < 16; j++) {
        float4 v = acc[j];
        v.x *= eb; v.y *= eb; v.z *= eb; v.w *= eb;
        pp[j] = v;
    }
}

// ---------------- inter-chunk combine: element-parallel, fp16 S out ------------
__global__ void __launch_bounds__(256) combine_kernel() {
    int g = blockIdx.x * 256 + threadIdx.x;
    int dv = g & 127, dk = (g >> 7) & 127, kv = g >> 14;
    float s = 0.f;
    for (int c = 0; c < NC; c++) {
        size_t idx = ((size_t)(c * 4 + kv) * 128 + dk) * 128 + dv;
        g_S16[idx] = __float2half_rn(s);
        float eb = g_EB[(size_t)(c * 4 + kv) * 128 + dk];
        s = eb * s + g_P[idx];
    }
}

// ---------------- intra-chunk output via mma + fused RMSNorm -------------------
#define OQ  0
#define OK  17408
#define OV  34816
#define OS  52224
#define OA  87040
#define OSMEM 96256

__global__ void __launch_bounds__(256) out_kernel(const float* __restrict__ gnw) {
    extern __shared__ char smraw[];
    uint32_t sb = smem_u32(smraw);
    float* sO = (float*)smraw;
    int c = blockIdx.x, h = blockIdx.y, kv = h >> 2;
    int tid = threadIdx.x, wid = tid >> 5, lane = tid & 31;
    int wm = wid >> 1, wn = wid & 1;

    {
        const __half* qg = g_q16 + (size_t)c * CH * 2048 + h * 128;
        const __half* kg = g_k16 + (size_t)c * CH * 512 + kv * 128;
        const __half* vg = g_v16 + (size_t)c * CH * 512 + kv * 128;
        const __half* sg = g_S16 + (size_t)(c * 4 + kv) * 16384;
        for (int u = tid; u < 5120; u += 256) {
            int r, ch;
            if (u < 1024) {
                r = u >> 4; ch = u & 15;
                cpa16(sb + OQ + r * 272 + ch * 16, qg + (size_t)r * 2048 + ch * 8);
            } else if (u < 2048) {
                int v = u - 1024; r = v >> 4; ch = v & 15;
                cpa16(sb + OK + r * 272 + ch * 16, kg + (size_t)r * 512 + ch * 8);
            } else if (u < 3072) {
                int v = u - 2048; r = v >> 4; ch = v & 15;
                cpa16(sb + OV + r * 272 + ch * 16, vg + (size_t)r * 512 + ch * 8);
            } else {
                int v = u - 3072; r = v >> 4; ch = v & 15;
                cpa16(sb + OS + r * 272 + ch * 16, sg + (size_t)r * 128 + ch * 8);
            }
        }
        asm volatile("cp.async.commit_group;" ::: "memory");
        asm volatile("cp.async.wait_group 0;" ::: "memory");
        __syncthreads();
    }

    int arow_l = (lane & 7) + ((lane >> 3) & 1) * 8;
    int acol   = (lane >> 4) * 8;
    int brow_l = (lane & 7) + ((lane >> 4) & 1) * 8;
    int bcol   = ((lane >> 3) & 1) * 8;
    int trow   = lane & 15;
    int tcol   = (lane >> 4) * 8;

    // phase 1: A = Q K^T (64x64), causal mask -> sA fp16
    {
        float aacc[4][4];
#pragma unroll
        for (int i = 0; i < 4; i++)
#pragma unroll
            for (int j = 0; j < 4; j++) aacc[i][j] = 0.f;
#pragma unroll
        for (int kk = 0; kk < 8; kk++) {
            uint32_t ar[4];
            ldsm4(ar, sb + OQ + (wm * 16 + arow_l) * 272 + (kk * 16 + acol) * 2);
            uint32_t br[2][4];
#pragma unroll
            for (int j = 0; j < 2; j++)
                ldsm4(br[j], sb + OK + (wn * 32 + j * 16 + brow_l) * 272 +
                              (kk * 16 + bcol) * 2);
#pragma unroll
            for (int jj = 0; jj < 4; jj++)
                mma16816(aacc[jj], ar,
                         br[jj >> 1][(jj & 1) * 2], br[jj >> 1][(jj & 1) * 2 + 1]);
        }
        __half* sA = (__half*)(smraw + OA);
        int rg = lane >> 2, cg = lane & 3;
#pragma unroll
        for (int jj = 0; jj < 4; jj++) {
            int col = wn * 32 + jj * 8 + cg * 2;
            int r0 = wm * 16 + rg;
            sA[r0 * 72 + col]     = __float2half_rn((col     <= r0) ? aacc[jj][0] : 0.f);
            sA[r0 * 72 + col + 1] = __float2half_rn((col + 1 <= r0) ? aacc[jj][1] : 0.f);
            int r1 = r0 + 8;
            sA[r1 * 72 + col]     = __float2half_rn((col     <= r1) ? aacc[jj][2] : 0.f);
            sA[r1 * 72 + col + 1] = __float2half_rn((col + 1 <= r1) ? aacc[jj][3] : 0.f);
        }
    }
    __syncthreads();

    // phase 2: O = Q S + A V (64x128), warp tile 16x64
    float oacc[8][4];
#pragma unroll
    for (int j = 0; j < 8; j++)
#pragma unroll
        for (int r = 0; r < 4; r++) oacc[j][r] = 0.f;

#pragma unroll
    for (int kk = 0; kk < 8; kk++) {
        uint32_t ar[4];
        ldsm4(ar, sb + OQ + (wm * 16 + arow_l) * 272 + (kk * 16 + acol) * 2);
        uint32_t bt[4][4];
#pragma unroll
        for (int jb = 0; jb < 4; jb++)
            ldsm4t(bt[jb], sb + OS + (kk * 16 + trow) * 272 +
                           (wn * 64 + jb * 16 + tcol) * 2);
#pragma unroll
        for (int j = 0; j < 8; j++)
            mma16816(oacc[j], ar,
                     bt[j >> 1][(j & 1) * 2], bt[j >> 1][(j & 1) * 2 + 1]);
    }
#pragma unroll
    for (int kk = 0; kk < 4; kk++) {
        uint32_t ar[4];
        ldsm4(ar, sb + OA + (wm * 16 + arow_l) * 144 + (kk * 16 + acol) * 2);
        uint32_t bt[4][4];
#pragma unroll
        for (int jb = 0; jb < 4; jb++)
            ldsm4t(bt[jb], sb + OV + (kk * 16 + trow) * 272 +
                           (wn * 64 + jb * 16 + tcol) * 2);
#pragma unroll
        for (int j = 0; j < 8; j++)
            mma16816(oacc[j], ar,
                     bt[j >> 1][(j & 1) * 2], bt[j >> 1][(j & 1) * 2 + 1]);
    }
    __syncthreads();

    {
        int rg = lane >> 2, cg = lane & 3;
#pragma unroll
        for (int j = 0; j < 8; j++) {
            int col = wn * 64 + j * 8 + cg * 2;
            int r0 = wm * 16 + rg;
            sO[r0 * 132 + col]       = oacc[j][0];
            sO[r0 * 132 + col + 1]   = oacc[j][1];
            sO[(r0 + 8) * 132 + col]     = oacc[j][2];
            sO[(r0 + 8) * 132 + col + 1] = oacc[j][3];
        }
    }
    __syncthreads();

    {
        int r = tid >> 2, q = tid & 3;
        const float* row = sO + r * 132 + q * 32;
        float ss = 0.f;
#pragma unroll
        for (int i = 0; i < 32; i++) ss += row[i] * row[i];
        ss += __shfl_xor_sync(0xffffffffu, ss, 1);
        ss += __shfl_xor_sync(0xffffffffu, ss, 2);
        float rn = rsqrtf(ss * (1.f / 128.f) + 1e-6f);
        __half* orow = g_oA16 + ((size_t)(c * CH) + r) * 2048 + h * 128 + q * 32;
#pragma unroll
        for (int i = 0; i < 32; i++)
            orow[i] = __float2half_rn(row[i] * rn * __ldg(gnw + q * 32 + i));
    }
}

// ---------------- launch -------------------------------------------------------
extern "C" void kernel_launch(void* const* d_in, const int* in_sizes, int n_in,
                              void* d_out, int out_size) {
    const float* hidden = (const float*)d_in[0];
    const float* Wqkv   = (const float*)d_in[1];
    const float* bqkv   = (const float*)d_in[2];
    const float* gk_w0  = (const float*)d_in[3];
    const float* gk_w1  = (const float*)d_in[4];
    const float* gk_b1  = (const float*)d_in[5];
    const float* gnormw = (const float*)d_in[6];
    const float* Wo     = (const float*)d_in[7];
    float* out = (float*)d_out;

    __half *p_hA16, *p_Wq16, *p_Wo16, *p_oA16;
    cudaGetSymbolAddress((void**)&p_hA16, g_hA16);
    cudaGetSymbolAddress((void**)&p_Wq16, g_Wq16);
    cudaGetSymbolAddress((void**)&p_Wo16, g_Wo16);
    cudaGetSymbolAddress((void**)&p_oA16, g_oA16);

    cudaFuncSetAttribute(gemm_mma, cudaFuncAttributeMaxDynamicSharedMemorySize, GSMEM);
    cudaFuncSetAttribute(out_kernel, cudaFuncAttributeMaxDynamicSharedMemorySize, OSMEM);

    // operand prep
    splitA16<<<(T_ * H_) / 1024, 256>>>(hidden, p_hA16);
    wtrans16<<<dim3(QKVW / 32, GK / 32), 256>>>(Wqkv, p_Wq16, QKVW);
    wtrans16<<<dim3(H_ / 32, GK / 32), 256>>>(Wo, p_Wo16, H_);

    // 1) qkv projection with fused bias/relu/scale -> fp16 q/k/v
    gemm_mma<<<dim3(QKVW / 256, T_ / 128), 512, GSMEM>>>(
        p_hA16, p_Wq16, bqkv, nullptr, QKVW, 1);

    // 2) gate projections
    gk1_kernel<<<T_, 256>>>(hidden, gk_w0);
    gk2_kernel<<<(T_ * 512) / 256, 256>>>(gk_w1, gk_b1);

    // 3) chunked GLA
    chunkB_kernel<<<dim3(NC, NKV_), 128>>>();
    chunkP_kernel<<<dim3(NC, NKV_), 256>>>();
    combine_kernel<<<256, 256>>>();
    out_kernel<<<dim3(NC, NH_), 256, OSMEM>>>(gnormw);

    // 4) o_proj
    gemm_mma<<<dim3(H_ / 256, T_ / 128), 512, GSMEM>>>(
        p_oA16, p_Wo16, nullptr, out, H_, 0);
}

// round 8
// speedup vs baseline: 6.0927x; 1.0825x over previous
#include <cuda_runtime.h>
#include <cuda_fp16.h>
#include <cstdint>
#include <math.h>

#define T_   8192
#define H_   2048
#define NH_  16
#define NKV_ 4
#define D_   128
#define CH   64
#define NC   128          // T_/CH
#define QKVW 3072
#define GK   2048

// ---------------- scratch (static device memory) ------------------------------
__device__ __align__(256) float g_tmp16[(size_t)T_ * 16];
__device__ __align__(256) float g_g[(size_t)T_ * 512];
__device__ __align__(256) float g_EB[(size_t)NC * NKV_ * D_];
__device__ __align__(256) float g_P[(size_t)NC * NKV_ * D_ * D_];
__device__ __align__(256) __half g_S16[(size_t)NC * NKV_ * D_ * D_];
// fp16 operands
__device__ __align__(256) __half g_hA16[(size_t)T_ * H_];
__device__ __align__(256) __half g_Wq16[(size_t)QKVW * GK];   // [N,K]
__device__ __align__(256) __half g_Wo16[(size_t)H_ * GK];     // [N,K]
__device__ __align__(256) __half g_oA16[(size_t)T_ * H_];
__device__ __align__(256) __half g_q16[(size_t)T_ * 2048];
__device__ __align__(256) __half g_k16[(size_t)T_ * 512];
__device__ __align__(256) __half g_v16[(size_t)T_ * 512];

// ======================= PTX helpers ==========================================
__device__ __forceinline__ uint32_t smem_u32(const void* p) {
    uint32_t a;
    asm("{ .reg .u64 t; cvta.to.shared.u64 t, %1; cvt.u32.u64 %0, t; }" : "=r"(a) : "l"(p));
    return a;
}
__device__ __forceinline__ void cpa16(uint32_t dst, const void* src) {
    asm volatile("cp.async.cg.shared.global [%0], [%1], 16;" :: "r"(dst), "l"(src));
}
__device__ __forceinline__ void ldsm4(uint32_t* r, uint32_t addr) {
    asm volatile("ldmatrix.sync.aligned.m8n8.x4.shared.b16 {%0,%1,%2,%3}, [%4];"
                 : "=r"(r[0]), "=r"(r[1]), "=r"(r[2]), "=r"(r[3]) : "r"(addr));
}
__device__ __forceinline__ void ldsm4t(uint32_t* r, uint32_t addr) {
    asm volatile("ldmatrix.sync.aligned.m8n8.x4.trans.shared.b16 {%0,%1,%2,%3}, [%4];"
                 : "=r"(r[0]), "=r"(r[1]), "=r"(r[2]), "=r"(r[3]) : "r"(addr));
}
__device__ __forceinline__ void mma16816(float* d, const uint32_t* a,
                                         uint32_t b0, uint32_t b1) {
    asm volatile("mma.sync.aligned.m16n8k16.row.col.f32.f16.f16.f32 "
                 "{%0,%1,%2,%3}, {%4,%5,%6,%7}, {%8,%9}, {%0,%1,%2,%3};"
                 : "+f"(d[0]), "+f"(d[1]), "+f"(d[2]), "+f"(d[3])
                 : "r"(a[0]), "r"(a[1]), "r"(a[2]), "r"(a[3]), "r"(b0), "r"(b1));
}

// ======================= conversions ==========================================
__global__ void __launch_bounds__(256) splitA16(const float* __restrict__ src,
                                                __half* __restrict__ dst) {
    size_t i4 = ((size_t)blockIdx.x * 256 + threadIdx.x) * 4;
    float4 v = *(const float4*)(src + i4);
    __half2* d = (__half2*)(dst + i4);
    d[0] = __floats2half2_rn(v.x, v.y);
    d[1] = __floats2half2_rn(v.z, v.w);
}

__global__ void __launch_bounds__(256) wtrans16(const float* __restrict__ W,
                                                __half* __restrict__ out, int N) {
    __shared__ float t[32][33];
    int bx = blockIdx.x, by = blockIdx.y;
    int lx = threadIdx.x & 31, ly = threadIdx.x >> 5;
    for (int r = ly; r < 32; r += 8)
        t[r][lx] = W[(size_t)(by * 32 + r) * N + bx * 32 + lx];
    __syncthreads();
    for (int r = ly; r < 32; r += 8)
        out[(size_t)(bx * 32 + r) * GK + by * 32 + lx] = __float2half_rn(t[lx][r]);
}

// ======================= HMMA GEMM: 256 thr, 128x128, 2 CTAs/SM ===============
// mode 1: qkv projection; epilogue writes fp16 q/k/v buffers directly.
// mode 0: writes fp32 C.
#define ROWB   80
#define TILEB  (128 * ROWB)          // 10240
#define STAGEB (2 * TILEB)           // 20480 (A + B)
#define GSMEM  (4 * STAGEB)          // 81920 -> 2 CTAs/SM

__global__ void __launch_bounds__(256) gemm_mma(
    const __half* __restrict__ A16, const __half* __restrict__ B16,
    const float* __restrict__ bias, float* __restrict__ C, int N, int mode) {
    extern __shared__ char smraw[];
    uint32_t sbase = smem_u32(smraw);
    int tid = threadIdx.x, wid = tid >> 5, lane = tid & 31;
    int tm = blockIdx.y * 128, tn = blockIdx.x * 128;
    int wm = wid & 1, wn = wid >> 1;      // warp tile 64(M) x 32(N)

    float acc[4][4][4];
#pragma unroll
    for (int i = 0; i < 4; i++)
#pragma unroll
        for (int j = 0; j < 4; j++)
#pragma unroll
            for (int r = 0; r < 4; r++) acc[i][j][r] = 0.f;

    auto issue_load = [&](int k0i, int stage) {
        int k0 = k0i * 32;
        uint32_t sb = sbase + stage * STAGEB;
#pragma unroll
        for (int it = 0; it < 4; it++) {
            int u = tid + it * 256;
            const __half* src;
            uint32_t dst;
            if (u < 512) {
                int row = u >> 2, chunk = u & 3;
                src = A16 + (size_t)(tm + row) * GK + k0 + chunk * 8;
                dst = sb + row * ROWB + chunk * 16;
            } else {
                int v = u - 512;
                int row = v >> 2, chunk = v & 3;
                src = B16 + (size_t)(tn + row) * GK + k0 + chunk * 8;
                dst = sb + TILEB + row * ROWB + chunk * 16;
            }
            cpa16(dst, src);
        }
        asm volatile("cp.async.commit_group;" ::: "memory");
    };

    issue_load(0, 0);
    issue_load(1, 1);
    issue_load(2, 2);

    int arow_l = (lane & 7) + ((lane >> 3) & 1) * 8;
    int acol   = (lane >> 4) * 8;
    int brow_l = (lane & 7) + ((lane >> 4) & 1) * 8;
    int bcol   = ((lane >> 3) & 1) * 8;

    for (int kc = 0; kc < 64; kc++) {
        if (kc < 62)       asm volatile("cp.async.wait_group 2;" ::: "memory");
        else if (kc == 62) asm volatile("cp.async.wait_group 1;" ::: "memory");
        else               asm volatile("cp.async.wait_group 0;" ::: "memory");
        __syncthreads();
        if (kc + 3 < 64) issue_load(kc + 3, (kc + 3) & 3);

        uint32_t sb = sbase + (kc & 3) * STAGEB;
#pragma unroll
        for (int ks = 0; ks < 2; ks++) {
            uint32_t a_regs[4][4];
#pragma unroll
            for (int i = 0; i < 4; i++)
                ldsm4(a_regs[i],
                      sb + (wm * 64 + i * 16 + arow_l) * ROWB + (ks * 16 + acol) * 2);
            uint32_t b_regs[2][4];
#pragma unroll
            for (int j = 0; j < 2; j++)
                ldsm4(b_regs[j], sb + TILEB +
                      (wn * 32 + j * 16 + brow_l) * ROWB + (ks * 16 + bcol) * 2);
#pragma unroll
            for (int i = 0; i < 4; i++)
#pragma unroll
                for (int jj = 0; jj < 4; jj++)
                    mma16816(acc[i][jj], a_regs[i],
                             b_regs[jj >> 1][(jj & 1) * 2],
                             b_regs[jj >> 1][(jj & 1) * 2 + 1]);
        }
    }

    int g = lane >> 2, tg = lane & 3;
#pragma unroll
    for (int i = 0; i < 4; i++) {
        int row0 = tm + wm * 64 + i * 16 + g;
#pragma unroll
        for (int jj = 0; jj < 4; jj++) {
            int col = tn + wn * 32 + jj * 8 + tg * 2;
            float v0 = acc[i][jj][0], v1 = acc[i][jj][1];
            float v2 = acc[i][jj][2], v3 = acc[i][jj][3];
            if (mode) {
                float b0 = bias[col], b1 = bias[col + 1];
                v0 += b0; v1 += b1; v2 += b0; v3 += b1;
                if (col < 2560) {
                    v0 = fmaxf(v0, 0.f); v1 = fmaxf(v1, 0.f);
                    v2 = fmaxf(v2, 0.f); v3 = fmaxf(v3, 0.f);
                    if (col < 2048) {
                        const float s = 0.08838834764831843f;
                        v0 *= s; v1 *= s; v2 *= s; v3 *= s;
                    }
                }
                __half2 h0 = __floats2half2_rn(v0, v1);
                __half2 h1 = __floats2half2_rn(v2, v3);
                if (col < 2048) {
                    *(__half2*)(g_q16 + (size_t)row0 * 2048 + col) = h0;
                    *(__half2*)(g_q16 + (size_t)(row0 + 8) * 2048 + col) = h1;
                } else if (col < 2560) {
                    *(__half2*)(g_k16 + (size_t)row0 * 512 + col - 2048) = h0;
                    *(__half2*)(g_k16 + (size_t)(row0 + 8) * 512 + col - 2048) = h1;
                } else {
                    *(__half2*)(g_v16 + (size_t)row0 * 512 + col - 2560) = h0;
                    *(__half2*)(g_v16 + (size_t)(row0 + 8) * 512 + col - 2560) = h1;
                }
            } else {
                *(float2*)(C + (size_t)row0 * N + col)       = make_float2(v0, v1);
                *(float2*)(C + (size_t)(row0 + 8) * N + col) = make_float2(v2, v3);
            }
        }
    }
}

// ---------------- gate low-rank projections -----------------------------------
__global__ void __launch_bounds__(256) gk1_kernel(const float* __restrict__ hidden,
                                                  const float* __restrict__ w0) {
    int t = blockIdx.x, tid = threadIdx.x;
    float acc[16];
#pragma unroll
    for (int r = 0; r < 16; r++) acc[r] = 0.f;
    const float* hrow = hidden + (size_t)t * H_;
    for (int h = tid; h < H_; h += 256) {
        float x = hrow[h];
        const float4* w = (const float4*)(w0 + (size_t)h * 16);
#pragma unroll
        for (int q = 0; q < 4; q++) {
            float4 w4 = w[q];
            acc[q * 4 + 0] += x * w4.x;
            acc[q * 4 + 1] += x * w4.y;
            acc[q * 4 + 2] += x * w4.z;
            acc[q * 4 + 3] += x * w4.w;
        }
    }
    __shared__ float sred[256][16];
#pragma unroll
    for (int r = 0; r < 16; r++) sred[tid][r] = acc[r];
    __syncthreads();
    if (tid < 16) {
        float s = 0.f;
        for (int i = 0; i < 256; i++) s += sred[i][tid];
        g_tmp16[(size_t)t * 16 + tid] = s;
    }
}

__global__ void __launch_bounds__(256) gk2_kernel(const float* __restrict__ w1,
                                                  const float* __restrict__ b1) {
    int idx = blockIdx.x * 256 + threadIdx.x;
    int t = idx >> 9, n = idx & 511;
    const float* tp = g_tmp16 + (size_t)t * 16;
    float x = b1[n];
#pragma unroll
    for (int r = 0; r < 16; r++) x += tp[r] * w1[r * 512 + n];
    float ls = (x >= 0.f) ? (-log1pf(expf(-x))) : (x - log1pf(expf(x)));
    g_g[(size_t)t * 512 + n] = ls * (1.f / 16.f);
}

// ---------------- per-chunk cumsum + fp16 q/k scaling in place ----------------
__global__ void __launch_bounds__(128) chunkB_kernel() {
    int c = blockIdx.x, kv = blockIdx.y, d = threadIdx.x;
    float cum = 0.f;
    for (int t = 0; t < CH; t++) {
        size_t tg = (size_t)c * CH + t;
        cum += g_g[tg * 512 + kv * 128 + d];
        float eB = expf(cum), eBn = expf(-cum);
        size_t ok = tg * 512 + kv * 128 + d;
        g_k16[ok] = __float2half_rn(__half2float(g_k16[ok]) * eBn);
#pragma unroll
        for (int r = 0; r < 4; r++) {
            size_t oq = tg * 2048 + (kv * 4 + r) * 128 + d;
            g_q16[oq] = __float2half_rn(__half2float(g_q16[oq]) * eB);
        }
    }
    g_EB[(size_t)(c * 4 + kv) * 128 + d] = expf(cum);
}

// ---------------- per-chunk increment P = exp(Btot) ⊙ (K~^T V) ----------------
__global__ void __launch_bounds__(256) chunkP_kernel() {
    __shared__ float sv[CH * 128];
    int c = blockIdx.x, kv = blockIdx.y, tid = threadIdx.x;
    for (int i = tid; i < CH * 64; i += 256) {
        int r = i >> 6, c2 = i & 63;
        __half2 hv = *(const __half2*)(g_v16 + ((size_t)(c * CH + r)) * 512 +
                                       kv * 128 + c2 * 2);
        float2 f = __half22float2(hv);
        sv[r * 128 + c2 * 2] = f.x;
        sv[r * 128 + c2 * 2 + 1] = f.y;
    }
    __syncthreads();
    int dk = tid >> 1, half = (tid & 1) * 64;
    float4 acc[16];
#pragma unroll
    for (int j = 0; j < 16; j++) acc[j] = make_float4(0.f, 0.f, 0.f, 0.f);
    for (int t = 0; t < CH; t++) {
        float kk = __half2float(g_k16[((size_t)(c * CH + t)) * 512 + kv * 128 + dk]);
        const float4* vr = (const float4*)(sv + t * 128 + half);
#pragma unroll
        for (int j = 0; j < 16; j++) {
            float4 v = vr[j];
            acc[j].x += kk * v.x; acc[j].y += kk * v.y;
            acc[j].z += kk * v.z; acc[j].w += kk * v.w;
        }
    }
    float eb = g_EB[(size_t)(c * 4 + kv) * 128 + dk];
    float4* pp = (float4*)(g_P + (((size_t)(c * 4 + kv)) * 128 + dk) * 128 + half);
#pragma unroll
    for (int j = 0; j < 16; j++) {
        float4 v = acc[j];
        v.x *= eb; v.y *= eb; v.z *= eb; v.w *= eb;
        pp[j] = v;
    }
}

// ---------------- inter-chunk combine: element-parallel, fp16 S out ------------
__global__ void __launch_bounds__(256) combine_kernel() {
    int g = blockIdx.x * 256 + threadIdx.x;
    int dv = g & 127, dk = (g >> 7) & 127, kv = g >> 14;
    float s = 0.f;
    for (int c = 0; c < NC; c++) {
        size_t idx = ((size_t)(c * 4 + kv) * 128 + dk) * 128 + dv;
        g_S16[idx] = __float2half_rn(s);
        float eb = g_EB[(size_t)(c * 4 + kv) * 128 + dk];
        s = eb * s + g_P[idx];
    }
}

// ---------------- intra-chunk output via mma + fused RMSNorm -------------------
#define OQ  0
#define OK  17408
#define OV  34816
#define OS  52224
#define OA  87040
#define OSMEM 96256

__global__ void __launch_bounds__(256) out_kernel(const float* __restrict__ gnw) {
    extern __shared__ char smraw[];
    uint32_t sb = smem_u32(smraw);
    float* sO = (float*)smraw;
    int c = blockIdx.x, h = blockIdx.y, kv = h >> 2;
    int tid = threadIdx.x, wid = tid >> 5, lane = tid & 31;
    int wm = wid >> 1, wn = wid & 1;

    {
        const __half* qg = g_q16 + (size_t)c * CH * 2048 + h * 128;
        const __half* kg = g_k16 + (size_t)c * CH * 512 + kv * 128;
        const __half* vg = g_v16 + (size_t)c * CH * 512 + kv * 128;
        const __half* sg = g_S16 + (size_t)(c * 4 + kv) * 16384;
        for (int u = tid; u < 5120; u += 256) {
            int r, ch;
            if (u < 1024) {
                r = u >> 4; ch = u & 15;
                cpa16(sb + OQ + r * 272 + ch * 16, qg + (size_t)r * 2048 + ch * 8);
            } else if (u < 2048) {
                int v = u - 1024; r = v >> 4; ch = v & 15;
                cpa16(sb + OK + r * 272 + ch * 16, kg + (size_t)r * 512 + ch * 8);
            } else if (u < 3072) {
                int v = u - 2048; r = v >> 4; ch = v & 15;
                cpa16(sb + OV + r * 272 + ch * 16, vg + (size_t)r * 512 + ch * 8);
            } else {
                int v = u - 3072; r = v >> 4; ch = v & 15;
                cpa16(sb + OS + r * 272 + ch * 16, sg + (size_t)r * 128 + ch * 8);
            }
        }
        asm volatile("cp.async.commit_group;" ::: "memory");
        asm volatile("cp.async.wait_group 0;" ::: "memory");
        __syncthreads();
    }

    int arow_l = (lane & 7) + ((lane >> 3) & 1) * 8;
    int acol   = (lane >> 4) * 8;
    int brow_l = (lane & 7) + ((lane >> 4) & 1) * 8;
    int bcol   = ((lane >> 3) & 1) * 8;
    int trow   = lane & 15;
    int tcol   = (lane >> 4) * 8;

    // phase 1: A = Q K^T (64x64), causal mask -> sA fp16
    {
        float aacc[4][4];
#pragma unroll
        for (int i = 0; i < 4; i++)
#pragma unroll
            for (int j = 0; j < 4; j++) aacc[i][j] = 0.f;
#pragma unroll
        for (int kk = 0; kk < 8; kk++) {
            uint32_t ar[4];
            ldsm4(ar, sb + OQ + (wm * 16 + arow_l) * 272 + (kk * 16 + acol) * 2);
            uint32_t br[2][4];
#pragma unroll
            for (int j = 0; j < 2; j++)
                ldsm4(br[j], sb + OK + (wn * 32 + j * 16 + brow_l) * 272 +
                              (kk * 16 + bcol) * 2);
#pragma unroll
            for (int jj = 0; jj < 4; jj++)
                mma16816(aacc[jj], ar,
                         br[jj >> 1][(jj & 1) * 2], br[jj >> 1][(jj & 1) * 2 + 1]);
        }
        __half* sA = (__half*)(smraw + OA);
        int rg = lane >> 2, cg = lane & 3;
#pragma unroll
        for (int jj = 0; jj < 4; jj++) {
            int col = wn * 32 + jj * 8 + cg * 2;
            int r0 = wm * 16 + rg;
            sA[r0 * 72 + col]     = __float2half_rn((col     <= r0) ? aacc[jj][0] : 0.f);
            sA[r0 * 72 + col + 1] = __float2half_rn((col + 1 <= r0) ? aacc[jj][1] : 0.f);
            int r1 = r0 + 8;
            sA[r1 * 72 + col]     = __float2half_rn((col     <= r1) ? aacc[jj][2] : 0.f);
            sA[r1 * 72 + col + 1] = __float2half_rn((col + 1 <= r1) ? aacc[jj][3] : 0.f);
        }
    }
    __syncthreads();

    // phase 2: O = Q S + A V (64x128), warp tile 16x64
    float oacc[8][4];
#pragma unroll
    for (int j = 0; j < 8; j++)
#pragma unroll
        for (int r = 0; r < 4; r++) oacc[j][r] = 0.f;

#pragma unroll
    for (int kk = 0; kk < 8; kk++) {
        uint32_t ar[4];
        ldsm4(ar, sb + OQ + (wm * 16 + arow_l) * 272 + (kk * 16 + acol) * 2);
        uint32_t bt[4][4];
#pragma unroll
        for (int jb = 0; jb < 4; jb++)
            ldsm4t(bt[jb], sb + OS + (kk * 16 + trow) * 272 +
                           (wn * 64 + jb * 16 + tcol) * 2);
#pragma unroll
        for (int j = 0; j < 8; j++)
            mma16816(oacc[j], ar,
                     bt[j >> 1][(j & 1) * 2], bt[j >> 1][(j & 1) * 2 + 1]);
    }
#pragma unroll
    for (int kk = 0; kk < 4; kk++) {
        uint32_t ar[4];
        ldsm4(ar, sb + OA + (wm * 16 + arow_l) * 144 + (kk * 16 + acol) * 2);
        uint32_t bt[4][4];
#pragma unroll
        for (int jb = 0; jb < 4; jb++)
            ldsm4t(bt[jb], sb + OV + (kk * 16 + trow) * 272 +
                           (wn * 64 + jb * 16 + tcol) * 2);
#pragma unroll
        for (int j = 0; j < 8; j++)
            mma16816(oacc[j], ar,
                     bt[j >> 1][(j & 1) * 2], bt[j >> 1][(j & 1) * 2 + 1]);
    }
    __syncthreads();

    {
        int rg = lane >> 2, cg = lane & 3;
#pragma unroll
        for (int j = 0; j < 8; j++) {
            int col = wn * 64 + j * 8 + cg * 2;
            int r0 = wm * 16 + rg;
            sO[r0 * 132 + col]       = oacc[j][0];
            sO[r0 * 132 + col + 1]   = oacc[j][1];
            sO[(r0 + 8) * 132 + col]     = oacc[j][2];
            sO[(r0 + 8) * 132 + col + 1] = oacc[j][3];
        }
    }
    __syncthreads();

    {
        int r = tid >> 2, q = tid & 3;
        const float* row = sO + r * 132 + q * 32;
        float ss = 0.f;
#pragma unroll
        for (int i = 0; i < 32; i++) ss += row[i] * row[i];
        ss += __shfl_xor_sync(0xffffffffu, ss, 1);
        ss += __shfl_xor_sync(0xffffffffu, ss, 2);
        float rn = rsqrtf(ss * (1.f / 128.f) + 1e-6f);
        __half* orow = g_oA16 + ((size_t)(c * CH) + r) * 2048 + h * 128 + q * 32;
#pragma unroll
        for (int i = 0; i < 32; i++)
            orow[i] = __float2half_rn(row[i] * rn * __ldg(gnw + q * 32 + i));
    }
}

// ---------------- launch -------------------------------------------------------
extern "C" void kernel_launch(void* const* d_in, const int* in_sizes, int n_in,
                              void* d_out, int out_size) {
    const float* hidden = (const float*)d_in[0];
    const float* Wqkv   = (const float*)d_in[1];
    const float* bqkv   = (const float*)d_in[2];
    const float* gk_w0  = (const float*)d_in[3];
    const float* gk_w1  = (const float*)d_in[4];
    const float* gk_b1  = (const float*)d_in[5];
    const float* gnormw = (const float*)d_in[6];
    const float* Wo     = (const float*)d_in[7];
    float* out = (float*)d_out;

    __half *p_hA16, *p_Wq16, *p_Wo16, *p_oA16;
    cudaGetSymbolAddress((void**)&p_hA16, g_hA16);
    cudaGetSymbolAddress((void**)&p_Wq16, g_Wq16);
    cudaGetSymbolAddress((void**)&p_Wo16, g_Wo16);
    cudaGetSymbolAddress((void**)&p_oA16, g_oA16);

    cudaFuncSetAttribute(gemm_mma, cudaFuncAttributeMaxDynamicSharedMemorySize, GSMEM);
    cudaFuncSetAttribute(out_kernel, cudaFuncAttributeMaxDynamicSharedMemorySize, OSMEM);

    // operand prep
    splitA16<<<(T_ * H_) / 1024, 256>>>(hidden, p_hA16);
    wtrans16<<<dim3(QKVW / 32, GK / 32), 256>>>(Wqkv, p_Wq16, QKVW);
    wtrans16<<<dim3(H_ / 32, GK / 32), 256>>>(Wo, p_Wo16, H_);

    // 1) qkv projection with fused bias/relu/scale -> fp16 q/k/v
    gemm_mma<<<dim3(QKVW / 128, T_ / 128), 256, GSMEM>>>(
        p_hA16, p_Wq16, bqkv, nullptr, QKVW, 1);

    // 2) gate projections
    gk1_kernel<<<T_, 256>>>(hidden, gk_w0);
    gk2_kernel<<<(T_ * 512) / 256, 256>>>(gk_w1, gk_b1);

    // 3) chunked GLA
    chunkB_kernel<<<dim3(NC, NKV_), 128>>>();
    chunkP_kernel<<<dim3(NC, NKV_), 256>>>();
    combine_kernel<<<256, 256>>>();
    out_kernel<<<dim3(NC, NH_), 256, OSMEM>>>(gnormw);

    // 4) o_proj
    gemm_mma<<<dim3(H_ / 128, T_ / 128), 256, GSMEM>>>(
        p_oA16, p_Wo16, nullptr, out, H_, 0);
}